// round 10
// baseline (speedup 1.0000x reference)
#include <cuda_runtime.h>
#include <cuda_bf16.h>
#include <math_constants.h>
#include <cstdint>

// Problem constants
#define NN      20000
#define EE      320000
#define NODE_D  128
#define EDGE_D  16
#define HC      512       // HEADS*EMB
#define HEADS   4
#define EMB     128
#define HIDDEN  512
#define OUTD    64
#define NEG_SLOPE 0.2f

// ---------------- scratch (device globals; no allocation allowed) -------------
__device__ int   g_is64;
__device__ int   g_cnt[NN];
__device__ int   g_off[NN + 1];
__device__ int   g_cur[NN];
__device__ int   g_csr_src[EE];
__device__ int   g_csr_eid[EE];
__device__ float g_loop[NN * EDGE_D];
__device__ float g_Wp[HC * 1024];             // packed+rounded weights (max 512x1024)
__device__ float g_bp[1024];                  // packed bias
__device__ float g_xA[(size_t)NN * NODE_D];   // tf32-rounded copy of x
__device__ float g_xlr[(size_t)NN * 1024];    // [N][1024]: xl | xr (reused as decoder hidden)
__device__ float g_h[(size_t)NN * HC];        // layer outputs (tf32-rounded)

// ---------------- helpers -----------------------------------------------------
__device__ __forceinline__ int edge_val(const void* p, int is64, long long i) {
    return is64 ? (int)((const long long*)p)[i] : ((const int*)p)[i];
}

__device__ __forceinline__ float rna_tf32(float f) {
    unsigned u;
    asm("cvt.rna.tf32.f32 %0, %1;" : "=r"(u) : "f"(f));
    return __uint_as_float(u);
}

// zero counters + detect int64 vs int32 edge_index
__global__ void init_kernel(const void* eidx) {
    int i = blockIdx.x * blockDim.x + threadIdx.x;
    if (i < NN) { g_cnt[i] = 0; g_cur[i] = 0; }
    if (i == 0) {
        const unsigned* p = (const unsigned*)eidx;
        int is64 = 1;
        for (int k = 0; k < 16; k++)
            if (p[2 * k + 1] != 0u) is64 = 0;
        g_is64 = is64;
    }
}

__global__ void count_kernel(const void* eidx) {
    int e = blockIdx.x * blockDim.x + threadIdx.x;
    if (e >= EE) return;
    int is64 = g_is64;
    int dst = edge_val(eidx, is64, (long long)EE + e);
    atomicAdd(&g_cnt[dst], 1);
}

__global__ __launch_bounds__(1024) void scan_kernel() {
    __shared__ int s[1024];
    int tid = threadIdx.x;
    const int per = (NN + 1023) >> 10;
    int start = tid * per;
    int sum = 0;
    for (int i = 0; i < per; i++) {
        int idx = start + i;
        if (idx < NN) sum += g_cnt[idx];
    }
    s[tid] = sum;
    __syncthreads();
    for (int o = 1; o < 1024; o <<= 1) {
        int v = 0;
        if (tid >= o) v = s[tid - o];
        __syncthreads();
        if (tid >= o) s[tid] += v;
        __syncthreads();
    }
    int base = (tid > 0) ? s[tid - 1] : 0;
    for (int i = 0; i < per; i++) {
        int idx = start + i;
        if (idx < NN) { g_off[idx] = base; base += g_cnt[idx]; }
    }
    if (tid == 1023) g_off[NN] = s[1023];
}

__global__ void scatter_kernel(const void* eidx) {
    int e = blockIdx.x * blockDim.x + threadIdx.x;
    if (e >= EE) return;
    int is64 = g_is64;
    int src = edge_val(eidx, is64, e);
    int dst = edge_val(eidx, is64, (long long)EE + e);
    int pos = g_off[dst] + atomicAdd(&g_cur[dst], 1);
    g_csr_src[pos] = src;
    g_csr_eid[pos] = e;
}

// self-loop attr = mean of incoming edge_attr (CSR-based, no atomics)
__global__ __launch_bounds__(128) void loopattr_kernel(const float* __restrict__ ea) {
    int n = blockIdx.x * 4 + (threadIdx.x >> 5);
    if (n >= NN) return;
    int lane = threadIdx.x & 31;
    int beg = g_off[n], end = g_off[n + 1];
    float sum = 0.f;
    if (lane < EDGE_D) {
        for (int i = beg; i < end; i++) {
            int eid = g_csr_eid[i];
            sum += __ldg(&ea[(size_t)eid * EDGE_D + lane]);
        }
        float c = (float)(end - beg);
        g_loop[n * EDGE_D + lane] = sum / fmaxf(c, 1.f);
    }
}

// tf32-round x into g_xA
__global__ void round_x_kernel(const float* __restrict__ x) {
    int i = blockIdx.x * blockDim.x + threadIdx.x;
    if (i < NN * NODE_D) g_xA[i] = rna_tf32(x[i]);
}

// pack [W0|W1] (split at col S) into g_Wp with tf32 rounding; bias into g_bp
__global__ void pack_kernel(const float* __restrict__ W0, const float* __restrict__ W1,
                            const float* __restrict__ b0, const float* __restrict__ b1,
                            int S, int Nn, int K) {
    int i = blockIdx.x * blockDim.x + threadIdx.x;
    if (i < K * Nn) {
        int k = i / Nn, j = i - k * Nn;
        float v = (j < S) ? W0[k * S + j] : W1[k * (Nn - S) + (j - S)];
        g_Wp[i] = rna_tf32(v);
    }
    if (i < Nn) g_bp[i] = (i < S) ? b0[i] : b1[i - S];
}

// ---------------- tf32 tensor-core GEMM (3-stage cp.async pipeline) -----------
// Operands must already be tf32-rounded in memory. 256 threads, 64x32 warp tile.
#define BMt 128
#define BNt 128
#define BKt 32
#define AS_STRIDE 36
#define BS_STRIDE 136
#define AS_SIZE (BMt * AS_STRIDE)            // floats
#define BS_SIZE (BKt * BS_STRIDE)
#define STAGE_FLOATS (AS_SIZE + BS_SIZE)     // 8960 floats = 35840 B
#define GEMM_SMEM (3 * STAGE_FLOATS * 4)     // 107520 B

__device__ __forceinline__ void cp16(uint32_t dst, const float* src, int sz) {
    asm volatile("cp.async.cg.shared.global [%0], [%1], 16, %2;\n"
                 :: "r"(dst), "l"(src), "r"(sz));
}
__device__ __forceinline__ void cp_commit() {
    asm volatile("cp.async.commit_group;\n" ::: "memory");
}

// 256 threads. A: thread loads row tid>>1, 16-float half (4 x 16B).
// B: thread loads row tid>>3, 16-float chunk (4 x 16B).
__device__ __forceinline__ void load_tiles(
    uint32_t as_u, uint32_t bs_u, const float* aptr, const float* __restrict__ B,
    int kt, int buf, int a_sz, int brow, int colBase, int bcol, int Nn)
{
    uint32_t ad = as_u + buf * (STAGE_FLOATS * 4);
    const float* ap = aptr + kt;
#pragma unroll
    for (int i = 0; i < 4; i++) cp16(ad + i * 16, ap + i * 4, a_sz);
    uint32_t bd = bs_u + buf * (STAGE_FLOATS * 4);
    const float* bp = B + (size_t)(kt + brow) * Nn + colBase + bcol;
#pragma unroll
    for (int i = 0; i < 4; i++) {
        int gcol = colBase + bcol + i * 4;
        cp16(bd + i * 16, bp + i * 4, (gcol < Nn) ? 16 : 0);
    }
}

__global__ __launch_bounds__(256, 2) void gemm_tc_kernel(
    const float* __restrict__ A, const float* __restrict__ B,
    const float* __restrict__ bias, float* __restrict__ C,
    int M, int Nn, int K, int relu, int round_out)
{
    extern __shared__ float sm[];   // 3 stages of [A(128x36) | B(32x136)]

    int tid  = threadIdx.x;
    int warp = tid >> 5;
    int lane = tid & 31;
    int gid  = lane >> 2;
    int tg   = lane & 3;

    int warpM = (warp & 1) * 64;   // 2 warps over M
    int warpN = (warp >> 1) * 32;  // 4 warps over N

    int rowBase = blockIdx.y * BMt;
    int colBase = blockIdx.x * BNt;

    float acc[4][4][4];
#pragma unroll
    for (int i = 0; i < 4; i++)
#pragma unroll
        for (int j = 0; j < 4; j++)
#pragma unroll
            for (int r = 0; r < 4; r++) acc[i][j][r] = 0.f;

    // loader indices
    int arow = tid >> 1;                 // 0..127
    int acol = (tid & 1) * 16;           // 0 or 16
    int brow = tid >> 3;                 // 0..31
    int bcol = (tid & 7) * 16;           // 0..112
    int agrow = rowBase + arow;
    const float* aptr = A + (size_t)agrow * K + acol;
    int a_sz = (agrow < M) ? 16 : 0;

    uint32_t smem_u = (uint32_t)__cvta_generic_to_shared(sm);
    uint32_t as_u = smem_u + (arow * AS_STRIDE + acol) * 4;
    uint32_t bs_u = smem_u + (AS_SIZE + brow * BS_STRIDE + bcol) * 4;

    int nTiles = K / BKt;
    load_tiles(as_u, bs_u, aptr, B, 0, 0, a_sz, brow, colBase, bcol, Nn);
    cp_commit();
    if (nTiles > 1) {
        load_tiles(as_u, bs_u, aptr, B, BKt, 1, a_sz, brow, colBase, bcol, Nn);
        cp_commit();
    }

    int buf = 0;
    for (int t = 0; t < nTiles; t++) {
        if (t + 1 < nTiles) {
            asm volatile("cp.async.wait_group 1;\n" ::: "memory");
        } else {
            asm volatile("cp.async.wait_group 0;\n" ::: "memory");
        }
        __syncthreads();

        if (t + 2 < nTiles) {
            int nbuf = buf + 2; if (nbuf >= 3) nbuf -= 3;
            load_tiles(as_u, bs_u, aptr, B, (t + 2) * BKt, nbuf, a_sz, brow, colBase, bcol, Nn);
            cp_commit();
        }

        const float* Ab = sm + buf * STAGE_FLOATS;
        const float* Bb = Ab + AS_SIZE;
#pragma unroll
        for (int ks = 0; ks < 4; ks++) {
            int k0 = ks * 8;
            unsigned af[4][4], bf[4][2];
#pragma unroll
            for (int mt = 0; mt < 4; mt++) {
                int r = warpM + mt * 16;
                af[mt][0] = __float_as_uint(Ab[(r + gid) * AS_STRIDE + k0 + tg]);
                af[mt][1] = __float_as_uint(Ab[(r + gid + 8) * AS_STRIDE + k0 + tg]);
                af[mt][2] = __float_as_uint(Ab[(r + gid) * AS_STRIDE + k0 + tg + 4]);
                af[mt][3] = __float_as_uint(Ab[(r + gid + 8) * AS_STRIDE + k0 + tg + 4]);
            }
#pragma unroll
            for (int nt = 0; nt < 4; nt++) {
                int c = warpN + nt * 8;
                bf[nt][0] = __float_as_uint(Bb[(k0 + tg) * BS_STRIDE + c + gid]);
                bf[nt][1] = __float_as_uint(Bb[(k0 + tg + 4) * BS_STRIDE + c + gid]);
            }
#pragma unroll
            for (int mt = 0; mt < 4; mt++)
#pragma unroll
                for (int nt = 0; nt < 4; nt++) {
                    asm volatile(
                        "mma.sync.aligned.m16n8k8.row.col.f32.tf32.tf32.f32 "
                        "{%0,%1,%2,%3}, {%4,%5,%6,%7}, {%8,%9}, {%0,%1,%2,%3};"
                        : "+f"(acc[mt][nt][0]), "+f"(acc[mt][nt][1]),
                          "+f"(acc[mt][nt][2]), "+f"(acc[mt][nt][3])
                        : "r"(af[mt][0]), "r"(af[mt][1]), "r"(af[mt][2]), "r"(af[mt][3]),
                          "r"(bf[nt][0]), "r"(bf[nt][1]));
                }
        }
        buf++; if (buf >= 3) buf -= 3;
    }

    // epilogue: float2 stores (adjacent cols per thread)
#pragma unroll
    for (int mt = 0; mt < 4; mt++) {
#pragma unroll
        for (int nt = 0; nt < 4; nt++) {
            int r0 = rowBase + warpM + mt * 16 + gid;
            int c0 = colBase + warpN + nt * 8 + tg * 2;
#pragma unroll
            for (int half = 0; half < 2; half++) {
                int row = r0 + half * 8;
                if (row < M && c0 < Nn) {   // Nn even, c0 even -> pair-granular
                    float v0 = acc[mt][nt][half * 2 + 0] + bias[c0];
                    float v1 = acc[mt][nt][half * 2 + 1] + bias[c0 + 1];
                    if (relu) { v0 = fmaxf(v0, 0.f); v1 = fmaxf(v1, 0.f); }
                    if (round_out) { v0 = rna_tf32(v0); v1 = rna_tf32(v1); }
                    *(float2*)&C[(size_t)row * Nn + c0] = make_float2(v0, v1);
                }
            }
        }
    }
}

// ---------------- GATv2 aggregation: one block / node, one warp / head --------
// We pre-transposed in smem: We_t[head][d][lane][4] so each lane's 4 channel
// weights load with one LDS.128.
__global__ __launch_bounds__(128) void gat_kernel(
    const float* __restrict__ xlr,        // [N][1024] xl|xr
    const float* __restrict__ edge_attr,  // [E][16]
    const float* __restrict__ We,         // [16][512]
    const float* __restrict__ att,        // [512]
    const float* __restrict__ bias,       // [512]
    float* __restrict__ out)              // [N][512] (tf32-rounded: feeds GEMMs only)
{
    __shared__ float We_t[HEADS * EDGE_D * 128];  // [w][d][lane*4+q]
    for (int i = threadIdx.x; i < HEADS * EDGE_D * 128; i += 128) {
        int w_ = i >> 11;            // /2048
        int rem = i & 2047;
        int d_ = rem >> 7;           // /128
        int r_ = rem & 127;
        int lane_ = r_ >> 2;
        int q_ = r_ & 3;
        We_t[i] = We[d_ * HC + w_ * EMB + q_ * 32 + lane_];
    }
    __syncthreads();

    int w = threadIdx.x >> 5;
    int lane = threadIdx.x & 31;
    int cbase = w * EMB + lane;
    const float4* Wt = (const float4*)&We_t[w * (EDGE_D * 128) + lane * 4];
    // Wt[d * 32] = float4 of We[d][cbase + {0,32,64,96}]

    float att0 = __ldg(&att[cbase]);
    float att1 = __ldg(&att[cbase + 32]);
    float att2 = __ldg(&att[cbase + 64]);
    float att3 = __ldg(&att[cbase + 96]);

    int n = blockIdx.x;

    const float* xrp = xlr + (size_t)n * 1024 + HC + cbase;
    float xr0 = xrp[0], xr1 = xrp[32], xr2 = xrp[64], xr3 = xrp[96];

    float m = -CUDART_INF_F, den = 0.f;
    float a0 = 0.f, a1 = 0.f, a2 = 0.f, a3 = 0.f;

    int beg = g_off[n], end = g_off[n + 1];

#define LOAD_EDGE(IDX, SRC, EAV) do {                                        \
        const float* _ea;                                                    \
        if ((IDX) < end) {                                                   \
            SRC = __ldg(&g_csr_src[IDX]);                                    \
            _ea = edge_attr + (size_t)__ldg(&g_csr_eid[IDX]) * EDGE_D;       \
        } else {                                                             \
            SRC = n;                                                         \
            _ea = g_loop + (size_t)n * EDGE_D;                               \
        }                                                                    \
        EAV = (lane < EDGE_D) ? __ldg(&_ea[lane]) : 0.f;                     \
    } while (0)

#define LOAD_X(SRC, X0, X1, X2, X3) do {                                     \
        const float* _xp = xlr + (size_t)(SRC) * 1024 + cbase;               \
        X0 = __ldg(&_xp[0]);  X1 = __ldg(&_xp[32]);                          \
        X2 = __ldg(&_xp[64]); X3 = __ldg(&_xp[96]);                          \
    } while (0)

    int src; float eav;
    float x0, x1, x2, x3;
    LOAD_EDGE(beg, src, eav);
    LOAD_X(src, x0, x1, x2, x3);

    for (int idx = beg; idx <= end; idx++) {
        float cx0 = x0, cx1 = x1, cx2 = x2, cx3 = x3;
        float ce = eav;

        if (idx < end) {                    // prefetch next edge
            LOAD_EDGE(idx + 1, src, eav);
            LOAD_X(src, x0, x1, x2, x3);
        }

        float e0 = xr0, e1 = xr1, e2 = xr2, e3 = xr3;
#pragma unroll
        for (int d = 0; d < EDGE_D; d++) {
            float av = __shfl_sync(0xffffffffu, ce, d);
            float4 wv = Wt[d * 32];
            e0 = fmaf(av, wv.x, e0);
            e1 = fmaf(av, wv.y, e1);
            e2 = fmaf(av, wv.z, e2);
            e3 = fmaf(av, wv.w, e3);
        }
        float s0 = cx0 + e0, s1 = cx1 + e1, s2 = cx2 + e2, s3 = cx3 + e3;
        float l0 = fmaxf(s0, NEG_SLOPE * s0);
        float l1 = fmaxf(s1, NEG_SLOPE * s1);
        float l2 = fmaxf(s2, NEG_SLOPE * s2);
        float l3 = fmaxf(s3, NEG_SLOPE * s3);

        float p = l0 * att0;
        p = fmaf(l1, att1, p);
        p = fmaf(l2, att2, p);
        p = fmaf(l3, att3, p);
#pragma unroll
        for (int o = 16; o > 0; o >>= 1) p += __shfl_xor_sync(0xffffffffu, p, o);

        float nm = fmaxf(m, p);
        float corr = __expf(m - nm);
        float pe   = __expf(p - nm);
        den = den * corr + pe;
        a0 = a0 * corr + pe * cx0;
        a1 = a1 * corr + pe * cx1;
        a2 = a2 * corr + pe * cx2;
        a3 = a3 * corr + pe * cx3;
        m = nm;
    }
    float inv = 1.f / (den + 1e-16f);
    float* op = out + (size_t)n * HC + cbase;
    op[0]  = rna_tf32(fmaf(a0, inv, __ldg(&bias[cbase])));
    op[32] = rna_tf32(fmaf(a1, inv, __ldg(&bias[cbase + 32])));
    op[64] = rna_tf32(fmaf(a2, inv, __ldg(&bias[cbase + 64])));
    op[96] = rna_tf32(fmaf(a3, inv, __ldg(&bias[cbase + 96])));
#undef LOAD_EDGE
#undef LOAD_X
}

// ---------------- launch ------------------------------------------------------
extern "C" void kernel_launch(void* const* d_in, const int* in_sizes, int n_in,
                              void* d_out, int out_size) {
    const float* x     = (const float*)d_in[0];
    const void*  eidx  = d_in[1];
    const float* eattr = (const float*)d_in[2];
    const float* Wl1   = (const float*)d_in[3];
    const float* bl1   = (const float*)d_in[4];
    const float* Wr1   = (const float*)d_in[5];
    const float* br1   = (const float*)d_in[6];
    const float* We1   = (const float*)d_in[7];
    const float* att1  = (const float*)d_in[8];
    const float* bias1 = (const float*)d_in[9];
    const float* Wl2   = (const float*)d_in[10];
    const float* bl2   = (const float*)d_in[11];
    const float* Wr2   = (const float*)d_in[12];
    const float* br2   = (const float*)d_in[13];
    const float* We2   = (const float*)d_in[14];
    const float* att2  = (const float*)d_in[15];
    const float* bias2 = (const float*)d_in[16];
    const float* Wd1   = (const float*)d_in[17];
    const float* bd1   = (const float*)d_in[18];
    const float* Wd2   = (const float*)d_in[19];
    const float* bd2   = (const float*)d_in[20];
    float* out = (float*)d_out;

    float* xlr; cudaGetSymbolAddress((void**)&xlr, g_xlr);
    float* h;   cudaGetSymbolAddress((void**)&h, g_h);
    float* xA;  cudaGetSymbolAddress((void**)&xA, g_xA);
    float* Wp;  cudaGetSymbolAddress((void**)&Wp, g_Wp);
    float* bp;  cudaGetSymbolAddress((void**)&bp, g_bp);

    cudaFuncSetAttribute(gemm_tc_kernel,
                         cudaFuncAttributeMaxDynamicSharedMemorySize, GEMM_SMEM);

    dim3 blk(256);
    dim3 grid_lr(1024 / BNt, (NN + BMt - 1) / BMt);
    dim3 grid_d1((HIDDEN + BNt - 1) / BNt, (NN + BMt - 1) / BMt);
    dim3 grid_d2((OUTD + BNt - 1) / BNt, (NN + BMt - 1) / BMt);

    // ---- layer-1 GEMM first (ncu capture lands here) ----
    init_kernel<<<(NN + 255) / 256, 256>>>(eidx);
    round_x_kernel<<<(NN * NODE_D + 255) / 256, 256>>>(x);
    pack_kernel<<<(NODE_D * 1024 + 255) / 256, 256>>>(Wl1, Wr1, bl1, br1, HC, 1024, NODE_D);
    gemm_tc_kernel<<<grid_lr, blk, GEMM_SMEM>>>(xA, Wp, bp, xlr, NN, 1024, NODE_D, 0, 0);

    // ---- CSR preprocessing ----
    count_kernel<<<(EE + 255) / 256, 256>>>(eidx);
    scan_kernel<<<1, 1024>>>();
    scatter_kernel<<<(EE + 255) / 256, 256>>>(eidx);
    loopattr_kernel<<<(NN + 3) / 4, 128>>>(eattr);

    // ---- layer 1 aggregation ----
    gat_kernel<<<NN, 128>>>(xlr, eattr, We1, att1, bias1, h);

    // ---- layer 2 ----
    pack_kernel<<<(HC * 1024 + 255) / 256, 256>>>(Wl2, Wr2, bl2, br2, HC, 1024, HC);
    gemm_tc_kernel<<<grid_lr, blk, GEMM_SMEM>>>(h, Wp, bp, xlr, NN, 1024, HC, 0, 0);
    gat_kernel<<<NN, 128>>>(xlr, eattr, We2, att2, bias2, h);

    // ---- decoder ----
    float* hid = xlr;  // reuse scratch
    pack_kernel<<<(HC * HIDDEN + 255) / 256, 256>>>(Wd1, Wd1, bd1, bd1, HIDDEN, HIDDEN, HC);
    gemm_tc_kernel<<<grid_d1, blk, GEMM_SMEM>>>(h, Wp, bp, hid, NN, HIDDEN, HC, 1, 1);
    pack_kernel<<<(HIDDEN * OUTD + 255) / 256, 256>>>(Wd2, Wd2, bd2, bd2, OUTD, OUTD, HIDDEN);
    gemm_tc_kernel<<<grid_d2, blk, GEMM_SMEM>>>(hid, Wp, bp, out, NN, OUTD, HIDDEN, 0, 0);
}

// round 11
// speedup vs baseline: 1.7252x; 1.7252x over previous
#include <cuda_runtime.h>
#include <cuda_bf16.h>
#include <math_constants.h>
#include <cstdint>

// Problem constants
#define NN      20000
#define EE      320000
#define NODE_D  128
#define EDGE_D  16
#define HC      512       // HEADS*EMB
#define HEADS   4
#define EMB     128
#define HIDDEN  512
#define OUTD    64
#define NEG_SLOPE 0.2f

// ---------------- scratch (device globals; no allocation allowed) -------------
__device__ int   g_is64;
__device__ int   g_cnt[NN];
__device__ int   g_off[NN + 1];
__device__ int   g_cur[NN];
__device__ int   g_csr_src[EE];
__device__ int   g_csr_eid[EE];
__device__ float g_loop[NN * EDGE_D];
__device__ float g_Wp[HC * 1024];             // packed+rounded weights (max 512x1024)
__device__ float g_bp[1024];                  // packed bias
__device__ float g_xA[(size_t)NN * NODE_D];   // tf32-rounded copy of x
__device__ float g_xlr[(size_t)NN * 1024];    // [N][1024]: xl | xr (reused as decoder hidden)
__device__ float g_h[(size_t)NN * HC];        // layer outputs (tf32-rounded)

// ---------------- helpers -----------------------------------------------------
__device__ __forceinline__ int edge_val(const void* p, int is64, long long i) {
    return is64 ? (int)((const long long*)p)[i] : ((const int*)p)[i];
}

__device__ __forceinline__ float rna_tf32(float f) {
    unsigned u;
    asm("cvt.rna.tf32.f32 %0, %1;" : "=r"(u) : "f"(f));
    return __uint_as_float(u);
}

// zero counters + detect int64 vs int32 edge_index
__global__ void init_kernel(const void* eidx) {
    int i = blockIdx.x * blockDim.x + threadIdx.x;
    if (i < NN) { g_cnt[i] = 0; g_cur[i] = 0; }
    if (i == 0) {
        const unsigned* p = (const unsigned*)eidx;
        int is64 = 1;
        for (int k = 0; k < 16; k++)
            if (p[2 * k + 1] != 0u) is64 = 0;
        g_is64 = is64;
    }
}

__global__ void count_kernel(const void* eidx) {
    int e = blockIdx.x * blockDim.x + threadIdx.x;
    if (e >= EE) return;
    int is64 = g_is64;
    int dst = edge_val(eidx, is64, (long long)EE + e);
    atomicAdd(&g_cnt[dst], 1);
}

__global__ __launch_bounds__(1024) void scan_kernel() {
    __shared__ int s[1024];
    int tid = threadIdx.x;
    const int per = (NN + 1023) >> 10;
    int start = tid * per;
    int sum = 0;
    for (int i = 0; i < per; i++) {
        int idx = start + i;
        if (idx < NN) sum += g_cnt[idx];
    }
    s[tid] = sum;
    __syncthreads();
    for (int o = 1; o < 1024; o <<= 1) {
        int v = 0;
        if (tid >= o) v = s[tid - o];
        __syncthreads();
        if (tid >= o) s[tid] += v;
        __syncthreads();
    }
    int base = (tid > 0) ? s[tid - 1] : 0;
    for (int i = 0; i < per; i++) {
        int idx = start + i;
        if (idx < NN) { g_off[idx] = base; base += g_cnt[idx]; }
    }
    if (tid == 1023) g_off[NN] = s[1023];
}

__global__ void scatter_kernel(const void* eidx) {
    int e = blockIdx.x * blockDim.x + threadIdx.x;
    if (e >= EE) return;
    int is64 = g_is64;
    int src = edge_val(eidx, is64, e);
    int dst = edge_val(eidx, is64, (long long)EE + e);
    int pos = g_off[dst] + atomicAdd(&g_cur[dst], 1);
    g_csr_src[pos] = src;
    g_csr_eid[pos] = e;
}

// self-loop attr = mean of incoming edge_attr (CSR-based, no atomics)
__global__ __launch_bounds__(128) void loopattr_kernel(const float* __restrict__ ea) {
    int n = blockIdx.x * 4 + (threadIdx.x >> 5);
    if (n >= NN) return;
    int lane = threadIdx.x & 31;
    int beg = g_off[n], end = g_off[n + 1];
    float sum = 0.f;
    if (lane < EDGE_D) {
        for (int i = beg; i < end; i++) {
            int eid = g_csr_eid[i];
            sum += __ldg(&ea[(size_t)eid * EDGE_D + lane]);
        }
        float c = (float)(end - beg);
        g_loop[n * EDGE_D + lane] = sum / fmaxf(c, 1.f);
    }
}

// tf32-round x into g_xA
__global__ void round_x_kernel(const float* __restrict__ x) {
    int i = blockIdx.x * blockDim.x + threadIdx.x;
    if (i < NN * NODE_D) g_xA[i] = rna_tf32(x[i]);
}

// pack [W0|W1] (split at col S) into g_Wp with tf32 rounding; bias into g_bp
__global__ void pack_kernel(const float* __restrict__ W0, const float* __restrict__ W1,
                            const float* __restrict__ b0, const float* __restrict__ b1,
                            int S, int Nn, int K) {
    int i = blockIdx.x * blockDim.x + threadIdx.x;
    if (i < K * Nn) {
        int k = i / Nn, j = i - k * Nn;
        float v = (j < S) ? W0[k * S + j] : W1[k * (Nn - S) + (j - S)];
        g_Wp[i] = rna_tf32(v);
    }
    if (i < Nn) g_bp[i] = (i < S) ? b0[i] : b1[i - S];
}

// ---------------- tf32 tensor-core GEMM (3-stage cp.async pipeline) -----------
// Operands must already be tf32-rounded in memory. 256 threads, 64x32 warp tile.
#define BMt 128
#define BNt 128
#define BKt 32
#define AS_STRIDE 36
#define BS_STRIDE 136
#define AS_SIZE (BMt * AS_STRIDE)            // floats
#define BS_SIZE (BKt * BS_STRIDE)
#define STAGE_FLOATS (AS_SIZE + BS_SIZE)     // 8960 floats = 35840 B
#define GEMM_SMEM (3 * STAGE_FLOATS * 4)     // 107520 B

__device__ __forceinline__ void cp16(uint32_t dst, const float* src, int sz) {
    asm volatile("cp.async.cg.shared.global [%0], [%1], 16, %2;\n"
                 :: "r"(dst), "l"(src), "r"(sz));
}
__device__ __forceinline__ void cp_commit() {
    asm volatile("cp.async.commit_group;\n" ::: "memory");
}

// 256 threads. A: thread loads row tid>>1, 16-float half (4 x 16B).
// B: thread loads row tid>>3, 16-float chunk (4 x 16B).
__device__ __forceinline__ void load_tiles(
    uint32_t as_u, uint32_t bs_u, const float* aptr, const float* __restrict__ B,
    int kt, int buf, int a_sz, int brow, int colBase, int bcol, int Nn)
{
    uint32_t ad = as_u + buf * (STAGE_FLOATS * 4);
    const float* ap = aptr + kt;
#pragma unroll
    for (int i = 0; i < 4; i++) cp16(ad + i * 16, ap + i * 4, a_sz);
    uint32_t bd = bs_u + buf * (STAGE_FLOATS * 4);
    const float* bp = B + (size_t)(kt + brow) * Nn + colBase + bcol;
#pragma unroll
    for (int i = 0; i < 4; i++) {
        int gcol = colBase + bcol + i * 4;
        cp16(bd + i * 16, bp + i * 4, (gcol < Nn) ? 16 : 0);
    }
}

__global__ __launch_bounds__(256, 2) void gemm_tc_kernel(
    const float* __restrict__ A, const float* __restrict__ B,
    const float* __restrict__ bias, float* __restrict__ C,
    int M, int Nn, int K, int relu, int round_out)
{
    extern __shared__ float sm[];   // 3 stages of [A(128x36) | B(32x136)]

    int tid  = threadIdx.x;
    int warp = tid >> 5;
    int lane = tid & 31;
    int gid  = lane >> 2;
    int tg   = lane & 3;

    int warpM = (warp & 1) * 64;   // 2 warps over M
    int warpN = (warp >> 1) * 32;  // 4 warps over N

    int rowBase = blockIdx.y * BMt;
    int colBase = blockIdx.x * BNt;

    float acc[4][4][4];
#pragma unroll
    for (int i = 0; i < 4; i++)
#pragma unroll
        for (int j = 0; j < 4; j++)
#pragma unroll
            for (int r = 0; r < 4; r++) acc[i][j][r] = 0.f;

    // loader indices
    int arow = tid >> 1;                 // 0..127
    int acol = (tid & 1) * 16;           // 0 or 16
    int brow = tid >> 3;                 // 0..31
    int bcol = (tid & 7) * 16;           // 0..112
    int agrow = rowBase + arow;
    const float* aptr = A + (size_t)agrow * K + acol;
    int a_sz = (agrow < M) ? 16 : 0;

    uint32_t smem_u = (uint32_t)__cvta_generic_to_shared(sm);
    uint32_t as_u = smem_u + (arow * AS_STRIDE + acol) * 4;
    uint32_t bs_u = smem_u + (AS_SIZE + brow * BS_STRIDE + bcol) * 4;

    int nTiles = K / BKt;
    load_tiles(as_u, bs_u, aptr, B, 0, 0, a_sz, brow, colBase, bcol, Nn);
    cp_commit();
    if (nTiles > 1) {
        load_tiles(as_u, bs_u, aptr, B, BKt, 1, a_sz, brow, colBase, bcol, Nn);
        cp_commit();
    }

    int buf = 0;
    for (int t = 0; t < nTiles; t++) {
        if (t + 1 < nTiles) {
            asm volatile("cp.async.wait_group 1;\n" ::: "memory");
        } else {
            asm volatile("cp.async.wait_group 0;\n" ::: "memory");
        }
        __syncthreads();

        if (t + 2 < nTiles) {
            int nbuf = buf + 2; if (nbuf >= 3) nbuf -= 3;
            load_tiles(as_u, bs_u, aptr, B, (t + 2) * BKt, nbuf, a_sz, brow, colBase, bcol, Nn);
            cp_commit();
        }

        const float* Ab = sm + buf * STAGE_FLOATS;
        const float* Bb = Ab + AS_SIZE;
#pragma unroll
        for (int ks = 0; ks < 4; ks++) {
            int k0 = ks * 8;
            unsigned af[4][4], bf[4][2];
#pragma unroll
            for (int mt = 0; mt < 4; mt++) {
                int r = warpM + mt * 16;
                af[mt][0] = __float_as_uint(Ab[(r + gid) * AS_STRIDE + k0 + tg]);
                af[mt][1] = __float_as_uint(Ab[(r + gid + 8) * AS_STRIDE + k0 + tg]);
                af[mt][2] = __float_as_uint(Ab[(r + gid) * AS_STRIDE + k0 + tg + 4]);
                af[mt][3] = __float_as_uint(Ab[(r + gid + 8) * AS_STRIDE + k0 + tg + 4]);
            }
#pragma unroll
            for (int nt = 0; nt < 4; nt++) {
                int c = warpN + nt * 8;
                bf[nt][0] = __float_as_uint(Bb[(k0 + tg) * BS_STRIDE + c + gid]);
                bf[nt][1] = __float_as_uint(Bb[(k0 + tg + 4) * BS_STRIDE + c + gid]);
            }
#pragma unroll
            for (int mt = 0; mt < 4; mt++)
#pragma unroll
                for (int nt = 0; nt < 4; nt++) {
                    asm volatile(
                        "mma.sync.aligned.m16n8k8.row.col.f32.tf32.tf32.f32 "
                        "{%0,%1,%2,%3}, {%4,%5,%6,%7}, {%8,%9}, {%0,%1,%2,%3};"
                        : "+f"(acc[mt][nt][0]), "+f"(acc[mt][nt][1]),
                          "+f"(acc[mt][nt][2]), "+f"(acc[mt][nt][3])
                        : "r"(af[mt][0]), "r"(af[mt][1]), "r"(af[mt][2]), "r"(af[mt][3]),
                          "r"(bf[nt][0]), "r"(bf[nt][1]));
                }
        }
        buf++; if (buf >= 3) buf -= 3;
    }

    // epilogue
#pragma unroll
    for (int mt = 0; mt < 4; mt++) {
#pragma unroll
        for (int nt = 0; nt < 4; nt++) {
            int r0 = rowBase + warpM + mt * 16 + gid;
            int c0 = colBase + warpN + nt * 8 + tg * 2;
#pragma unroll
            for (int half = 0; half < 2; half++) {
                int row = r0 + half * 8;
                if (row < M) {
#pragma unroll
                    for (int j = 0; j < 2; j++) {
                        int col = c0 + j;
                        if (col < Nn) {
                            float v = acc[mt][nt][half * 2 + j] + bias[col];
                            if (relu) v = fmaxf(v, 0.f);
                            if (round_out) v = rna_tf32(v);
                            C[(size_t)row * Nn + col] = v;
                        }
                    }
                }
            }
        }
    }
}

// ---------------- GATv2 aggregation: 2 nodes / 256-thread block ---------------
// Warps 0-3 handle node 2b (one warp per head); warps 4-7 handle node 2b+1.
// One shared We_sh copy serves both nodes -> doubles node concurrency per SM
// at the same smem footprint.
__global__ __launch_bounds__(256) void gat_kernel(
    const float* __restrict__ xlr,        // [N][1024] xl|xr
    const float* __restrict__ edge_attr,  // [E][16]
    const float* __restrict__ We,         // [16][512]
    const float* __restrict__ att,        // [512]
    const float* __restrict__ bias,       // [512]
    float* __restrict__ out)              // [N][512] (tf32-rounded: feeds GEMMs only)
{
    __shared__ float We_sh[EDGE_D * HC];
    for (int i = threadIdx.x; i < EDGE_D * HC; i += 256) We_sh[i] = We[i];
    __syncthreads();

    int w = (threadIdx.x >> 5) & 3;           // head
    int lane = threadIdx.x & 31;
    int n = blockIdx.x * 2 + (threadIdx.x >> 7);   // node
    if (n >= NN) return;
    int cbase = w * EMB + lane;
    const float* Wp = We_sh + cbase;

    float att0 = __ldg(&att[cbase]);
    float att1 = __ldg(&att[cbase + 32]);
    float att2 = __ldg(&att[cbase + 64]);
    float att3 = __ldg(&att[cbase + 96]);

    const float* xrp = xlr + (size_t)n * 1024 + HC + cbase;
    float xr0 = xrp[0], xr1 = xrp[32], xr2 = xrp[64], xr3 = xrp[96];

    float m = -CUDART_INF_F, den = 0.f;
    float a0 = 0.f, a1 = 0.f, a2 = 0.f, a3 = 0.f;

    int beg = g_off[n], end = g_off[n + 1];

#define LOAD_EDGE(IDX, SRC, EAV) do {                                        \
        const float* _ea;                                                    \
        if ((IDX) < end) {                                                   \
            SRC = __ldg(&g_csr_src[IDX]);                                    \
            _ea = edge_attr + (size_t)__ldg(&g_csr_eid[IDX]) * EDGE_D;       \
        } else {                                                             \
            SRC = n;                                                         \
            _ea = g_loop + (size_t)n * EDGE_D;                               \
        }                                                                    \
        EAV = (lane < EDGE_D) ? __ldg(&_ea[lane]) : 0.f;                     \
    } while (0)

#define LOAD_X(SRC, X0, X1, X2, X3) do {                                     \
        const float* _xp = xlr + (size_t)(SRC) * 1024 + cbase;               \
        X0 = __ldg(&_xp[0]);  X1 = __ldg(&_xp[32]);                          \
        X2 = __ldg(&_xp[64]); X3 = __ldg(&_xp[96]);                          \
    } while (0)

    int src; float eav;
    float x0, x1, x2, x3;
    LOAD_EDGE(beg, src, eav);
    LOAD_X(src, x0, x1, x2, x3);

    for (int idx = beg; idx <= end; idx++) {
        float cx0 = x0, cx1 = x1, cx2 = x2, cx3 = x3;
        float ce = eav;

        if (idx < end) {                    // prefetch next edge
            LOAD_EDGE(idx + 1, src, eav);
            LOAD_X(src, x0, x1, x2, x3);
        }

        float e0 = xr0, e1 = xr1, e2 = xr2, e3 = xr3;
#pragma unroll
        for (int d = 0; d < EDGE_D; d++) {
            float av = __shfl_sync(0xffffffffu, ce, d);
            e0 = fmaf(av, Wp[d * HC], e0);
            e1 = fmaf(av, Wp[d * HC + 32], e1);
            e2 = fmaf(av, Wp[d * HC + 64], e2);
            e3 = fmaf(av, Wp[d * HC + 96], e3);
        }
        float s0 = cx0 + e0, s1 = cx1 + e1, s2 = cx2 + e2, s3 = cx3 + e3;
        float l0 = fmaxf(s0, NEG_SLOPE * s0);
        float l1 = fmaxf(s1, NEG_SLOPE * s1);
        float l2 = fmaxf(s2, NEG_SLOPE * s2);
        float l3 = fmaxf(s3, NEG_SLOPE * s3);

        float p = l0 * att0;
        p = fmaf(l1, att1, p);
        p = fmaf(l2, att2, p);
        p = fmaf(l3, att3, p);
#pragma unroll
        for (int o = 16; o > 0; o >>= 1) p += __shfl_xor_sync(0xffffffffu, p, o);

        float nm = fmaxf(m, p);
        float corr = __expf(m - nm);
        float pe   = __expf(p - nm);
        den = den * corr + pe;
        a0 = a0 * corr + pe * cx0;
        a1 = a1 * corr + pe * cx1;
        a2 = a2 * corr + pe * cx2;
        a3 = a3 * corr + pe * cx3;
        m = nm;
    }
    float inv = 1.f / (den + 1e-16f);
    float* op = out + (size_t)n * HC + cbase;
    op[0]  = rna_tf32(fmaf(a0, inv, __ldg(&bias[cbase])));
    op[32] = rna_tf32(fmaf(a1, inv, __ldg(&bias[cbase + 32])));
    op[64] = rna_tf32(fmaf(a2, inv, __ldg(&bias[cbase + 64])));
    op[96] = rna_tf32(fmaf(a3, inv, __ldg(&bias[cbase + 96])));
#undef LOAD_EDGE
#undef LOAD_X
}

// ---------------- launch ------------------------------------------------------
extern "C" void kernel_launch(void* const* d_in, const int* in_sizes, int n_in,
                              void* d_out, int out_size) {
    const float* x     = (const float*)d_in[0];
    const void*  eidx  = d_in[1];
    const float* eattr = (const float*)d_in[2];
    const float* Wl1   = (const float*)d_in[3];
    const float* bl1   = (const float*)d_in[4];
    const float* Wr1   = (const float*)d_in[5];
    const float* br1   = (const float*)d_in[6];
    const float* We1   = (const float*)d_in[7];
    const float* att1  = (const float*)d_in[8];
    const float* bias1 = (const float*)d_in[9];
    const float* Wl2   = (const float*)d_in[10];
    const float* bl2   = (const float*)d_in[11];
    const float* Wr2   = (const float*)d_in[12];
    const float* br2   = (const float*)d_in[13];
    const float* We2   = (const float*)d_in[14];
    const float* att2  = (const float*)d_in[15];
    const float* bias2 = (const float*)d_in[16];
    const float* Wd1   = (const float*)d_in[17];
    const float* bd1   = (const float*)d_in[18];
    const float* Wd2   = (const float*)d_in[19];
    const float* bd2   = (const float*)d_in[20];
    float* out = (float*)d_out;

    float* xlr; cudaGetSymbolAddress((void**)&xlr, g_xlr);
    float* h;   cudaGetSymbolAddress((void**)&h, g_h);
    float* xA;  cudaGetSymbolAddress((void**)&xA, g_xA);
    float* Wp;  cudaGetSymbolAddress((void**)&Wp, g_Wp);
    float* bp;  cudaGetSymbolAddress((void**)&bp, g_bp);

    cudaFuncSetAttribute(gemm_tc_kernel,
                         cudaFuncAttributeMaxDynamicSharedMemorySize, GEMM_SMEM);

    dim3 blk(256);
    dim3 grid_lr(1024 / BNt, (NN + BMt - 1) / BMt);
    dim3 grid_d1((HIDDEN + BNt - 1) / BNt, (NN + BMt - 1) / BMt);
    dim3 grid_d2((OUTD + BNt - 1) / BNt, (NN + BMt - 1) / BMt);

    // ---- layer-1 GEMM first (ncu capture lands here) ----
    init_kernel<<<(NN + 255) / 256, 256>>>(eidx);
    round_x_kernel<<<(NN * NODE_D + 255) / 256, 256>>>(x);
    pack_kernel<<<(NODE_D * 1024 + 255) / 256, 256>>>(Wl1, Wr1, bl1, br1, HC, 1024, NODE_D);
    gemm_tc_kernel<<<grid_lr, blk, GEMM_SMEM>>>(xA, Wp, bp, xlr, NN, 1024, NODE_D, 0, 0);

    // ---- CSR preprocessing ----
    count_kernel<<<(EE + 255) / 256, 256>>>(eidx);
    scan_kernel<<<1, 1024>>>();
    scatter_kernel<<<(EE + 255) / 256, 256>>>(eidx);
    loopattr_kernel<<<(NN + 3) / 4, 128>>>(eattr);

    // ---- layer 1 aggregation ----
    gat_kernel<<<NN / 2, 256>>>(xlr, eattr, We1, att1, bias1, h);

    // ---- layer 2 ----
    pack_kernel<<<(HC * 1024 + 255) / 256, 256>>>(Wl2, Wr2, bl2, br2, HC, 1024, HC);
    gemm_tc_kernel<<<grid_lr, blk, GEMM_SMEM>>>(h, Wp, bp, xlr, NN, 1024, HC, 0, 0);
    gat_kernel<<<NN / 2, 256>>>(xlr, eattr, We2, att2, bias2, h);

    // ---- decoder ----
    float* hid = xlr;  // reuse scratch
    pack_kernel<<<(HC * HIDDEN + 255) / 256, 256>>>(Wd1, Wd1, bd1, bd1, HIDDEN, HIDDEN, HC);
    gemm_tc_kernel<<<grid_d1, blk, GEMM_SMEM>>>(h, Wp, bp, hid, NN, HIDDEN, HC, 1, 1);
    pack_kernel<<<(HIDDEN * OUTD + 255) / 256, 256>>>(Wd2, Wd2, bd2, bd2, OUTD, OUTD, HIDDEN);
    gemm_tc_kernel<<<grid_d2, blk, GEMM_SMEM>>>(hid, Wp, bp, out, NN, OUTD, HIDDEN, 0, 0);
}

// round 12
// speedup vs baseline: 1.7281x; 1.0017x over previous
#include <cuda_runtime.h>
#include <cuda_bf16.h>
#include <math_constants.h>
#include <cstdint>

// Problem constants
#define NN      20000
#define EE      320000
#define NODE_D  128
#define EDGE_D  16
#define HC      512       // HEADS*EMB
#define HEADS   4
#define EMB     128
#define HIDDEN  512
#define OUTD    64
#define NEG_SLOPE 0.2f

// ---------------- scratch (device globals; no allocation allowed) -------------
__device__ int   g_is64;
__device__ int   g_cnt[NN];
__device__ int   g_off[NN + 1];
__device__ int   g_cur[NN];
__device__ int   g_csr_src[EE];
__device__ int   g_csr_eid[EE];
__device__ float g_loop[NN * EDGE_D];
__device__ float g_Wp[HC * 1024];             // packed+rounded weights (max 512x1024)
__device__ float g_bp[1024];                  // packed bias
__device__ float g_xA[(size_t)NN * NODE_D];   // tf32-rounded copy of x
__device__ float g_xlr[(size_t)NN * 1024];    // [N][1024]: xl | xr (reused as decoder hidden)
__device__ float g_h[(size_t)NN * HC];        // layer outputs (tf32-rounded)

// ---------------- helpers -----------------------------------------------------
__device__ __forceinline__ int edge_val(const void* p, int is64, long long i) {
    return is64 ? (int)((const long long*)p)[i] : ((const int*)p)[i];
}

__device__ __forceinline__ float rna_tf32(float f) {
    unsigned u;
    asm("cvt.rna.tf32.f32 %0, %1;" : "=r"(u) : "f"(f));
    return __uint_as_float(u);
}

// zero counters + detect int64 vs int32 edge_index
__global__ void init_kernel(const void* eidx) {
    int i = blockIdx.x * blockDim.x + threadIdx.x;
    if (i < NN) { g_cnt[i] = 0; g_cur[i] = 0; }
    if (i == 0) {
        const unsigned* p = (const unsigned*)eidx;
        int is64 = 1;
        for (int k = 0; k < 16; k++)
            if (p[2 * k + 1] != 0u) is64 = 0;
        g_is64 = is64;
    }
}

__global__ void count_kernel(const void* eidx) {
    int e = blockIdx.x * blockDim.x + threadIdx.x;
    if (e >= EE) return;
    int is64 = g_is64;
    int dst = edge_val(eidx, is64, (long long)EE + e);
    atomicAdd(&g_cnt[dst], 1);
}

__global__ __launch_bounds__(1024) void scan_kernel() {
    __shared__ int s[1024];
    int tid = threadIdx.x;
    const int per = (NN + 1023) >> 10;
    int start = tid * per;
    int sum = 0;
    for (int i = 0; i < per; i++) {
        int idx = start + i;
        if (idx < NN) sum += g_cnt[idx];
    }
    s[tid] = sum;
    __syncthreads();
    for (int o = 1; o < 1024; o <<= 1) {
        int v = 0;
        if (tid >= o) v = s[tid - o];
        __syncthreads();
        if (tid >= o) s[tid] += v;
        __syncthreads();
    }
    int base = (tid > 0) ? s[tid - 1] : 0;
    for (int i = 0; i < per; i++) {
        int idx = start + i;
        if (idx < NN) { g_off[idx] = base; base += g_cnt[idx]; }
    }
    if (tid == 1023) g_off[NN] = s[1023];
}

__global__ void scatter_kernel(const void* eidx) {
    int e = blockIdx.x * blockDim.x + threadIdx.x;
    if (e >= EE) return;
    int is64 = g_is64;
    int src = edge_val(eidx, is64, e);
    int dst = edge_val(eidx, is64, (long long)EE + e);
    int pos = g_off[dst] + atomicAdd(&g_cur[dst], 1);
    g_csr_src[pos] = src;
    g_csr_eid[pos] = e;
}

// self-loop attr = mean of incoming edge_attr (CSR-based, no atomics)
__global__ __launch_bounds__(128) void loopattr_kernel(const float* __restrict__ ea) {
    int n = blockIdx.x * 4 + (threadIdx.x >> 5);
    if (n >= NN) return;
    int lane = threadIdx.x & 31;
    int beg = g_off[n], end = g_off[n + 1];
    float sum = 0.f;
    if (lane < EDGE_D) {
        for (int i = beg; i < end; i++) {
            int eid = g_csr_eid[i];
            sum += __ldg(&ea[(size_t)eid * EDGE_D + lane]);
        }
        float c = (float)(end - beg);
        g_loop[n * EDGE_D + lane] = sum / fmaxf(c, 1.f);
    }
}

// tf32-round x into g_xA
__global__ void round_x_kernel(const float* __restrict__ x) {
    int i = blockIdx.x * blockDim.x + threadIdx.x;
    if (i < NN * NODE_D) g_xA[i] = rna_tf32(x[i]);
}

// pack [W0|W1] (split at col S) into g_Wp with tf32 rounding; bias into g_bp
__global__ void pack_kernel(const float* __restrict__ W0, const float* __restrict__ W1,
                            const float* __restrict__ b0, const float* __restrict__ b1,
                            int S, int Nn, int K) {
    int i = blockIdx.x * blockDim.x + threadIdx.x;
    if (i < K * Nn) {
        int k = i / Nn, j = i - k * Nn;
        float v = (j < S) ? W0[k * S + j] : W1[k * (Nn - S) + (j - S)];
        g_Wp[i] = rna_tf32(v);
    }
    if (i < Nn) g_bp[i] = (i < S) ? b0[i] : b1[i - S];
}

// ---------------- tf32 tensor-core GEMM (3-stage cp.async pipeline) -----------
// Operands must already be tf32-rounded in memory. 256 threads, 64x32 warp tile.
#define BMt 128
#define BNt 128
#define BKt 32
#define AS_STRIDE 36
#define BS_STRIDE 136
#define AS_SIZE (BMt * AS_STRIDE)            // floats
#define BS_SIZE (BKt * BS_STRIDE)
#define STAGE_FLOATS (AS_SIZE + BS_SIZE)     // 8960 floats = 35840 B
#define GEMM_SMEM (3 * STAGE_FLOATS * 4)     // 107520 B

__device__ __forceinline__ void cp16(uint32_t dst, const float* src, int sz) {
    asm volatile("cp.async.cg.shared.global [%0], [%1], 16, %2;\n"
                 :: "r"(dst), "l"(src), "r"(sz));
}
__device__ __forceinline__ void cp_commit() {
    asm volatile("cp.async.commit_group;\n" ::: "memory");
}

// 256 threads. A: thread loads row tid>>1, 16-float half (4 x 16B).
// B: thread loads row tid>>3, 16-float chunk (4 x 16B).
__device__ __forceinline__ void load_tiles(
    uint32_t as_u, uint32_t bs_u, const float* aptr, const float* __restrict__ B,
    int kt, int buf, int a_sz, int brow, int colBase, int bcol, int Nn)
{
    uint32_t ad = as_u + buf * (STAGE_FLOATS * 4);
    const float* ap = aptr + kt;
#pragma unroll
    for (int i = 0; i < 4; i++) cp16(ad + i * 16, ap + i * 4, a_sz);
    uint32_t bd = bs_u + buf * (STAGE_FLOATS * 4);
    const float* bp = B + (size_t)(kt + brow) * Nn + colBase + bcol;
#pragma unroll
    for (int i = 0; i < 4; i++) {
        int gcol = colBase + bcol + i * 4;
        cp16(bd + i * 16, bp + i * 4, (gcol < Nn) ? 16 : 0);
    }
}

__global__ __launch_bounds__(256, 2) void gemm_tc_kernel(
    const float* __restrict__ A, const float* __restrict__ B,
    const float* __restrict__ bias, float* __restrict__ C,
    int M, int Nn, int K, int relu, int round_out)
{
    extern __shared__ float sm[];   // 3 stages of [A(128x36) | B(32x136)]

    int tid  = threadIdx.x;
    int warp = tid >> 5;
    int lane = tid & 31;
    int gid  = lane >> 2;
    int tg   = lane & 3;

    int warpM = (warp & 1) * 64;   // 2 warps over M
    int warpN = (warp >> 1) * 32;  // 4 warps over N

    int rowBase = blockIdx.y * BMt;
    int colBase = blockIdx.x * BNt;

    float acc[4][4][4];
#pragma unroll
    for (int i = 0; i < 4; i++)
#pragma unroll
        for (int j = 0; j < 4; j++)
#pragma unroll
            for (int r = 0; r < 4; r++) acc[i][j][r] = 0.f;

    // loader indices
    int arow = tid >> 1;                 // 0..127
    int acol = (tid & 1) * 16;           // 0 or 16
    int brow = tid >> 3;                 // 0..31
    int bcol = (tid & 7) * 16;           // 0..112
    int agrow = rowBase + arow;
    const float* aptr = A + (size_t)agrow * K + acol;
    int a_sz = (agrow < M) ? 16 : 0;

    uint32_t smem_u = (uint32_t)__cvta_generic_to_shared(sm);
    uint32_t as_u = smem_u + (arow * AS_STRIDE + acol) * 4;
    uint32_t bs_u = smem_u + (AS_SIZE + brow * BS_STRIDE + bcol) * 4;

    int nTiles = K / BKt;
    load_tiles(as_u, bs_u, aptr, B, 0, 0, a_sz, brow, colBase, bcol, Nn);
    cp_commit();
    if (nTiles > 1) {
        load_tiles(as_u, bs_u, aptr, B, BKt, 1, a_sz, brow, colBase, bcol, Nn);
        cp_commit();
    }

    int buf = 0;
    for (int t = 0; t < nTiles; t++) {
        if (t + 1 < nTiles) {
            asm volatile("cp.async.wait_group 1;\n" ::: "memory");
        } else {
            asm volatile("cp.async.wait_group 0;\n" ::: "memory");
        }
        __syncthreads();

        if (t + 2 < nTiles) {
            int nbuf = buf + 2; if (nbuf >= 3) nbuf -= 3;
            load_tiles(as_u, bs_u, aptr, B, (t + 2) * BKt, nbuf, a_sz, brow, colBase, bcol, Nn);
            cp_commit();
        }

        const float* Ab = sm + buf * STAGE_FLOATS;
        const float* Bb = Ab + AS_SIZE;
#pragma unroll
        for (int ks = 0; ks < 4; ks++) {
            int k0 = ks * 8;
            unsigned af[4][4], bf[4][2];
#pragma unroll
            for (int mt = 0; mt < 4; mt++) {
                int r = warpM + mt * 16;
                af[mt][0] = __float_as_uint(Ab[(r + gid) * AS_STRIDE + k0 + tg]);
                af[mt][1] = __float_as_uint(Ab[(r + gid + 8) * AS_STRIDE + k0 + tg]);
                af[mt][2] = __float_as_uint(Ab[(r + gid) * AS_STRIDE + k0 + tg + 4]);
                af[mt][3] = __float_as_uint(Ab[(r + gid + 8) * AS_STRIDE + k0 + tg + 4]);
            }
#pragma unroll
            for (int nt = 0; nt < 4; nt++) {
                int c = warpN + nt * 8;
                bf[nt][0] = __float_as_uint(Bb[(k0 + tg) * BS_STRIDE + c + gid]);
                bf[nt][1] = __float_as_uint(Bb[(k0 + tg + 4) * BS_STRIDE + c + gid]);
            }
#pragma unroll
            for (int mt = 0; mt < 4; mt++)
#pragma unroll
                for (int nt = 0; nt < 4; nt++) {
                    asm volatile(
                        "mma.sync.aligned.m16n8k8.row.col.f32.tf32.tf32.f32 "
                        "{%0,%1,%2,%3}, {%4,%5,%6,%7}, {%8,%9}, {%0,%1,%2,%3};"
                        : "+f"(acc[mt][nt][0]), "+f"(acc[mt][nt][1]),
                          "+f"(acc[mt][nt][2]), "+f"(acc[mt][nt][3])
                        : "r"(af[mt][0]), "r"(af[mt][1]), "r"(af[mt][2]), "r"(af[mt][3]),
                          "r"(bf[nt][0]), "r"(bf[nt][1]));
                }
        }
        buf++; if (buf >= 3) buf -= 3;
    }

    // epilogue
#pragma unroll
    for (int mt = 0; mt < 4; mt++) {
#pragma unroll
        for (int nt = 0; nt < 4; nt++) {
            int r0 = rowBase + warpM + mt * 16 + gid;
            int c0 = colBase + warpN + nt * 8 + tg * 2;
#pragma unroll
            for (int half = 0; half < 2; half++) {
                int row = r0 + half * 8;
                if (row < M) {
#pragma unroll
                    for (int j = 0; j < 2; j++) {
                        int col = c0 + j;
                        if (col < Nn) {
                            float v = acc[mt][nt][half * 2 + j] + bias[col];
                            if (relu) v = fmaxf(v, 0.f);
                            if (round_out) v = rna_tf32(v);
                            C[(size_t)row * Nn + col] = v;
                        }
                    }
                }
            }
        }
    }
}

// ---------------- GATv2 aggregation: 2 nodes / 256-thread block ---------------
// Warps 0-3 handle node 2b; warps 4-7 node 2b+1. One We_sh serves both.
// 2-edge-deep software pipeline to cover L2 gather latency.
__global__ __launch_bounds__(256) void gat_kernel(
    const float* __restrict__ xlr,        // [N][1024] xl|xr
    const float* __restrict__ edge_attr,  // [E][16]
    const float* __restrict__ We,         // [16][512]
    const float* __restrict__ att,        // [512]
    const float* __restrict__ bias,       // [512]
    float* __restrict__ out)              // [N][512] (tf32-rounded: feeds GEMMs only)
{
    __shared__ float We_sh[EDGE_D * HC];
    for (int i = threadIdx.x; i < EDGE_D * HC; i += 256) We_sh[i] = We[i];
    __syncthreads();

    int w = (threadIdx.x >> 5) & 3;           // head
    int lane = threadIdx.x & 31;
    int n = blockIdx.x * 2 + (threadIdx.x >> 7);   // node
    if (n >= NN) return;
    int cbase = w * EMB + lane;
    const float* Wp = We_sh + cbase;

    float att0 = __ldg(&att[cbase]);
    float att1 = __ldg(&att[cbase + 32]);
    float att2 = __ldg(&att[cbase + 64]);
    float att3 = __ldg(&att[cbase + 96]);

    const float* xrp = xlr + (size_t)n * 1024 + HC + cbase;
    float xr0 = xrp[0], xr1 = xrp[32], xr2 = xrp[64], xr3 = xrp[96];

    float m = -CUDART_INF_F, den = 0.f;
    float a0 = 0.f, a1 = 0.f, a2 = 0.f, a3 = 0.f;

    int beg = g_off[n], end = g_off[n + 1];

#define LOAD_EDGE(IDX, SRC, EAV) do {                                        \
        const float* _ea;                                                    \
        if ((IDX) < end) {                                                   \
            SRC = __ldg(&g_csr_src[IDX]);                                    \
            _ea = edge_attr + (size_t)__ldg(&g_csr_eid[IDX]) * EDGE_D;       \
        } else {                                                             \
            SRC = n;                                                         \
            _ea = g_loop + (size_t)n * EDGE_D;                               \
        }                                                                    \
        EAV = (lane < EDGE_D) ? __ldg(&_ea[lane]) : 0.f;                     \
    } while (0)

#define LOAD_X(SRC, X0, X1, X2, X3) do {                                     \
        const float* _xp = xlr + (size_t)(SRC) * 1024 + cbase;               \
        X0 = __ldg(&_xp[0]);  X1 = __ldg(&_xp[32]);                          \
        X2 = __ldg(&_xp[64]); X3 = __ldg(&_xp[96]);                          \
    } while (0)

    // 2-deep pipeline state
    int src0 = n, src1 = n;
    float eav0 = 0.f, eav1 = 0.f;
    float x00 = 0.f, x01 = 0.f, x02 = 0.f, x03 = 0.f;
    float x10 = 0.f, x11 = 0.f, x12 = 0.f, x13 = 0.f;

    LOAD_EDGE(beg, src0, eav0);
    LOAD_X(src0, x00, x01, x02, x03);
    if (beg + 1 <= end) {
        LOAD_EDGE(beg + 1, src1, eav1);
        LOAD_X(src1, x10, x11, x12, x13);
    }

    for (int idx = beg; idx <= end; idx++) {
        float ce = eav0;
        float cx0 = x00, cx1 = x01, cx2 = x02, cx3 = x03;

        // shift slot1 -> slot0
        src0 = src1; eav0 = eav1;
        x00 = x10; x01 = x11; x02 = x12; x03 = x13;

        // prefetch edge idx+2
        if (idx + 2 <= end) {
            LOAD_EDGE(idx + 2, src1, eav1);
            LOAD_X(src1, x10, x11, x12, x13);
        }

        float e0 = xr0, e1 = xr1, e2 = xr2, e3 = xr3;
#pragma unroll
        for (int d = 0; d < EDGE_D; d++) {
            float av = __shfl_sync(0xffffffffu, ce, d);
            e0 = fmaf(av, Wp[d * HC], e0);
            e1 = fmaf(av, Wp[d * HC + 32], e1);
            e2 = fmaf(av, Wp[d * HC + 64], e2);
            e3 = fmaf(av, Wp[d * HC + 96], e3);
        }
        float s0 = cx0 + e0, s1 = cx1 + e1, s2 = cx2 + e2, s3 = cx3 + e3;
        float l0 = fmaxf(s0, NEG_SLOPE * s0);
        float l1 = fmaxf(s1, NEG_SLOPE * s1);
        float l2 = fmaxf(s2, NEG_SLOPE * s2);
        float l3 = fmaxf(s3, NEG_SLOPE * s3);

        float p = l0 * att0;
        p = fmaf(l1, att1, p);
        p = fmaf(l2, att2, p);
        p = fmaf(l3, att3, p);
#pragma unroll
        for (int o = 16; o > 0; o >>= 1) p += __shfl_xor_sync(0xffffffffu, p, o);

        float nm = fmaxf(m, p);
        float corr = __expf(m - nm);
        float pe   = __expf(p - nm);
        den = den * corr + pe;
        a0 = a0 * corr + pe * cx0;
        a1 = a1 * corr + pe * cx1;
        a2 = a2 * corr + pe * cx2;
        a3 = a3 * corr + pe * cx3;
        m = nm;
    }
    float inv = 1.f / (den + 1e-16f);
    float* op = out + (size_t)n * HC + cbase;
    op[0]  = rna_tf32(fmaf(a0, inv, __ldg(&bias[cbase])));
    op[32] = rna_tf32(fmaf(a1, inv, __ldg(&bias[cbase + 32])));
    op[64] = rna_tf32(fmaf(a2, inv, __ldg(&bias[cbase + 64])));
    op[96] = rna_tf32(fmaf(a3, inv, __ldg(&bias[cbase + 96])));
#undef LOAD_EDGE
#undef LOAD_X
}

// ---------------- launch ------------------------------------------------------
extern "C" void kernel_launch(void* const* d_in, const int* in_sizes, int n_in,
                              void* d_out, int out_size) {
    const float* x     = (const float*)d_in[0];
    const void*  eidx  = d_in[1];
    const float* eattr = (const float*)d_in[2];
    const float* Wl1   = (const float*)d_in[3];
    const float* bl1   = (const float*)d_in[4];
    const float* Wr1   = (const float*)d_in[5];
    const float* br1   = (const float*)d_in[6];
    const float* We1   = (const float*)d_in[7];
    const float* att1  = (const float*)d_in[8];
    const float* bias1 = (const float*)d_in[9];
    const float* Wl2   = (const float*)d_in[10];
    const float* bl2   = (const float*)d_in[11];
    const float* Wr2   = (const float*)d_in[12];
    const float* br2   = (const float*)d_in[13];
    const float* We2   = (const float*)d_in[14];
    const float* att2  = (const float*)d_in[15];
    const float* bias2 = (const float*)d_in[16];
    const float* Wd1   = (const float*)d_in[17];
    const float* bd1   = (const float*)d_in[18];
    const float* Wd2   = (const float*)d_in[19];
    const float* bd2   = (const float*)d_in[20];
    float* out = (float*)d_out;

    float* xlr; cudaGetSymbolAddress((void**)&xlr, g_xlr);
    float* h;   cudaGetSymbolAddress((void**)&h, g_h);
    float* xA;  cudaGetSymbolAddress((void**)&xA, g_xA);
    float* Wp;  cudaGetSymbolAddress((void**)&Wp, g_Wp);
    float* bp;  cudaGetSymbolAddress((void**)&bp, g_bp);

    cudaFuncSetAttribute(gemm_tc_kernel,
                         cudaFuncAttributeMaxDynamicSharedMemorySize, GEMM_SMEM);

    dim3 blk(256);
    dim3 grid_lr(1024 / BNt, (NN + BMt - 1) / BMt);
    dim3 grid_d1((HIDDEN + BNt - 1) / BNt, (NN + BMt - 1) / BMt);
    dim3 grid_d2((OUTD + BNt - 1) / BNt, (NN + BMt - 1) / BMt);

    // ---- layer-1 GEMM first (ncu capture lands here) ----
    init_kernel<<<(NN + 255) / 256, 256>>>(eidx);
    round_x_kernel<<<(NN * NODE_D + 255) / 256, 256>>>(x);
    pack_kernel<<<(NODE_D * 1024 + 255) / 256, 256>>>(Wl1, Wr1, bl1, br1, HC, 1024, NODE_D);
    gemm_tc_kernel<<<grid_lr, blk, GEMM_SMEM>>>(xA, Wp, bp, xlr, NN, 1024, NODE_D, 0, 0);

    // ---- CSR preprocessing ----
    count_kernel<<<(EE + 255) / 256, 256>>>(eidx);
    scan_kernel<<<1, 1024>>>();
    scatter_kernel<<<(EE + 255) / 256, 256>>>(eidx);
    loopattr_kernel<<<(NN + 3) / 4, 128>>>(eattr);

    // ---- layer 1 aggregation ----
    gat_kernel<<<NN / 2, 256>>>(xlr, eattr, We1, att1, bias1, h);

    // ---- layer 2 ----
    pack_kernel<<<(HC * 1024 + 255) / 256, 256>>>(Wl2, Wr2, bl2, br2, HC, 1024, HC);
    gemm_tc_kernel<<<grid_lr, blk, GEMM_SMEM>>>(h, Wp, bp, xlr, NN, 1024, HC, 0, 0);
    gat_kernel<<<NN / 2, 256>>>(xlr, eattr, We2, att2, bias2, h);

    // ---- decoder ----
    float* hid = xlr;  // reuse scratch
    pack_kernel<<<(HC * HIDDEN + 255) / 256, 256>>>(Wd1, Wd1, bd1, bd1, HIDDEN, HIDDEN, HC);
    gemm_tc_kernel<<<grid_d1, blk, GEMM_SMEM>>>(h, Wp, bp, hid, NN, HIDDEN, HC, 1, 1);
    pack_kernel<<<(HIDDEN * OUTD + 255) / 256, 256>>>(Wd2, Wd2, bd2, bd2, OUTD, OUTD, HIDDEN);
    gemm_tc_kernel<<<grid_d2, blk, GEMM_SMEM>>>(hid, Wp, bp, out, NN, OUTD, HIDDEN, 0, 0);
}

// round 13
// speedup vs baseline: 2.0868x; 1.2076x over previous
#include <cuda_runtime.h>
#include <cuda_bf16.h>
#include <math_constants.h>
#include <cstdint>

// Problem constants
#define NN      20000
#define EE      320000
#define NODE_D  128
#define EDGE_D  16
#define HC      512       // HEADS*EMB
#define HEADS   4
#define EMB     128
#define HIDDEN  512
#define OUTD    64
#define NEG_SLOPE 0.2f

// ---------------- scratch (device globals; no allocation allowed) -------------
__device__ int   g_is64;
__device__ int   g_cnt[NN];
__device__ int   g_off[NN + 1];
__device__ int   g_cur[NN];
__device__ int   g_csr_src[EE];
__device__ int   g_csr_eid[EE];
__device__ float g_loop[NN * EDGE_D];
__device__ float g_Wp[HC * 1024];             // packed+rounded weights (max 512x1024)
__device__ float g_bp[1024];                  // packed bias
__device__ float g_xA[(size_t)NN * NODE_D];   // tf32-rounded copy of x
__device__ float g_xlr[(size_t)NN * 1024];    // [N][1024]: xl | xr (reused as decoder hidden)
__device__ float g_h[(size_t)NN * HC];        // layer outputs (tf32-rounded)

// ---------------- helpers -----------------------------------------------------
__device__ __forceinline__ int edge_val(const void* p, int is64, long long i) {
    return is64 ? (int)((const long long*)p)[i] : ((const int*)p)[i];
}

__device__ __forceinline__ float rna_tf32(float f) {
    unsigned u;
    asm("cvt.rna.tf32.f32 %0, %1;" : "=r"(u) : "f"(f));
    return __uint_as_float(u);
}

// zero counters + detect int64 vs int32 edge_index
__global__ void init_kernel(const void* eidx) {
    int i = blockIdx.x * blockDim.x + threadIdx.x;
    if (i < NN) { g_cnt[i] = 0; g_cur[i] = 0; }
    if (i == 0) {
        const unsigned* p = (const unsigned*)eidx;
        int is64 = 1;
        for (int k = 0; k < 16; k++)
            if (p[2 * k + 1] != 0u) is64 = 0;
        g_is64 = is64;
    }
}

__global__ void count_kernel(const void* eidx) {
    int e = blockIdx.x * blockDim.x + threadIdx.x;
    if (e >= EE) return;
    int is64 = g_is64;
    int dst = edge_val(eidx, is64, (long long)EE + e);
    atomicAdd(&g_cnt[dst], 1);
}

__global__ __launch_bounds__(1024) void scan_kernel() {
    __shared__ int s[1024];
    int tid = threadIdx.x;
    const int per = (NN + 1023) >> 10;
    int start = tid * per;
    int sum = 0;
    for (int i = 0; i < per; i++) {
        int idx = start + i;
        if (idx < NN) sum += g_cnt[idx];
    }
    s[tid] = sum;
    __syncthreads();
    for (int o = 1; o < 1024; o <<= 1) {
        int v = 0;
        if (tid >= o) v = s[tid - o];
        __syncthreads();
        if (tid >= o) s[tid] += v;
        __syncthreads();
    }
    int base = (tid > 0) ? s[tid - 1] : 0;
    for (int i = 0; i < per; i++) {
        int idx = start + i;
        if (idx < NN) { g_off[idx] = base; base += g_cnt[idx]; }
    }
    if (tid == 1023) g_off[NN] = s[1023];
}

__global__ void scatter_kernel(const void* eidx) {
    int e = blockIdx.x * blockDim.x + threadIdx.x;
    if (e >= EE) return;
    int is64 = g_is64;
    int src = edge_val(eidx, is64, e);
    int dst = edge_val(eidx, is64, (long long)EE + e);
    int pos = g_off[dst] + atomicAdd(&g_cur[dst], 1);
    g_csr_src[pos] = src;
    g_csr_eid[pos] = e;
}

// self-loop attr = mean of incoming edge_attr (CSR-based, no atomics)
__global__ __launch_bounds__(128) void loopattr_kernel(const float* __restrict__ ea) {
    int n = blockIdx.x * 4 + (threadIdx.x >> 5);
    if (n >= NN) return;
    int lane = threadIdx.x & 31;
    int beg = g_off[n], end = g_off[n + 1];
    float sum = 0.f;
    if (lane < EDGE_D) {
        for (int i = beg; i < end; i++) {
            int eid = g_csr_eid[i];
            sum += __ldg(&ea[(size_t)eid * EDGE_D + lane]);
        }
        float c = (float)(end - beg);
        g_loop[n * EDGE_D + lane] = sum / fmaxf(c, 1.f);
    }
}

// tf32-round x into g_xA
__global__ void round_x_kernel(const float* __restrict__ x) {
    int i = blockIdx.x * blockDim.x + threadIdx.x;
    if (i < NN * NODE_D) g_xA[i] = rna_tf32(x[i]);
}

// pack [W0|W1] (split at col S) into g_Wp with tf32 rounding; bias into g_bp
__global__ void pack_kernel(const float* __restrict__ W0, const float* __restrict__ W1,
                            const float* __restrict__ b0, const float* __restrict__ b1,
                            int S, int Nn, int K) {
    int i = blockIdx.x * blockDim.x + threadIdx.x;
    if (i < K * Nn) {
        int k = i / Nn, j = i - k * Nn;
        float v = (j < S) ? W0[k * S + j] : W1[k * (Nn - S) + (j - S)];
        g_Wp[i] = rna_tf32(v);
    }
    if (i < Nn) g_bp[i] = (i < S) ? b0[i] : b1[i - S];
}

// ---------------- tf32 tensor-core GEMM (3-stage cp.async pipeline) -----------
// Operands must already be tf32-rounded in memory. 256 threads, 64x32 warp tile.
#define BMt 128
#define BNt 128
#define BKt 32
#define AS_STRIDE 36
#define BS_STRIDE 136
#define AS_SIZE (BMt * AS_STRIDE)            // floats
#define BS_SIZE (BKt * BS_STRIDE)
#define STAGE_FLOATS (AS_SIZE + BS_SIZE)     // 8960 floats = 35840 B
#define GEMM_SMEM (3 * STAGE_FLOATS * 4)     // 107520 B

__device__ __forceinline__ void cp16(uint32_t dst, const float* src, int sz) {
    asm volatile("cp.async.cg.shared.global [%0], [%1], 16, %2;\n"
                 :: "r"(dst), "l"(src), "r"(sz));
}
__device__ __forceinline__ void cp_commit() {
    asm volatile("cp.async.commit_group;\n" ::: "memory");
}

// 256 threads. A: thread loads row tid>>1, 16-float half (4 x 16B).
// B: thread loads row tid>>3, 16-float chunk (4 x 16B).
__device__ __forceinline__ void load_tiles(
    uint32_t as_u, uint32_t bs_u, const float* aptr, const float* __restrict__ B,
    int kt, int buf, int a_sz, int brow, int colBase, int bcol, int Nn)
{
    uint32_t ad = as_u + buf * (STAGE_FLOATS * 4);
    const float* ap = aptr + kt;
#pragma unroll
    for (int i = 0; i < 4; i++) cp16(ad + i * 16, ap + i * 4, a_sz);
    uint32_t bd = bs_u + buf * (STAGE_FLOATS * 4);
    const float* bp = B + (size_t)(kt + brow) * Nn + colBase + bcol;
#pragma unroll
    for (int i = 0; i < 4; i++) {
        int gcol = colBase + bcol + i * 4;
        cp16(bd + i * 16, bp + i * 4, (gcol < Nn) ? 16 : 0);
    }
}

__global__ __launch_bounds__(256, 2) void gemm_tc_kernel(
    const float* __restrict__ A, const float* __restrict__ B,
    const float* __restrict__ bias, float* __restrict__ C,
    int M, int Nn, int K, int relu, int round_out)
{
    extern __shared__ float sm[];   // 3 stages of [A(128x36) | B(32x136)]

    int tid  = threadIdx.x;
    int warp = tid >> 5;
    int lane = tid & 31;
    int gid  = lane >> 2;
    int tg   = lane & 3;

    int warpM = (warp & 1) * 64;   // 2 warps over M
    int warpN = (warp >> 1) * 32;  // 4 warps over N

    int rowBase = blockIdx.y * BMt;
    int colBase = blockIdx.x * BNt;

    float acc[4][4][4];
#pragma unroll
    for (int i = 0; i < 4; i++)
#pragma unroll
        for (int j = 0; j < 4; j++)
#pragma unroll
            for (int r = 0; r < 4; r++) acc[i][j][r] = 0.f;

    // loader indices
    int arow = tid >> 1;                 // 0..127
    int acol = (tid & 1) * 16;           // 0 or 16
    int brow = tid >> 3;                 // 0..31
    int bcol = (tid & 7) * 16;           // 0..112
    int agrow = rowBase + arow;
    const float* aptr = A + (size_t)agrow * K + acol;
    int a_sz = (agrow < M) ? 16 : 0;

    uint32_t smem_u = (uint32_t)__cvta_generic_to_shared(sm);
    uint32_t as_u = smem_u + (arow * AS_STRIDE + acol) * 4;
    uint32_t bs_u = smem_u + (AS_SIZE + brow * BS_STRIDE + bcol) * 4;

    int nTiles = K / BKt;
    load_tiles(as_u, bs_u, aptr, B, 0, 0, a_sz, brow, colBase, bcol, Nn);
    cp_commit();
    if (nTiles > 1) {
        load_tiles(as_u, bs_u, aptr, B, BKt, 1, a_sz, brow, colBase, bcol, Nn);
        cp_commit();
    }

    int buf = 0;
    for (int t = 0; t < nTiles; t++) {
        if (t + 1 < nTiles) {
            asm volatile("cp.async.wait_group 1;\n" ::: "memory");
        } else {
            asm volatile("cp.async.wait_group 0;\n" ::: "memory");
        }
        __syncthreads();

        if (t + 2 < nTiles) {
            int nbuf = buf + 2; if (nbuf >= 3) nbuf -= 3;
            load_tiles(as_u, bs_u, aptr, B, (t + 2) * BKt, nbuf, a_sz, brow, colBase, bcol, Nn);
            cp_commit();
        }

        const float* Ab = sm + buf * STAGE_FLOATS;
        const float* Bb = Ab + AS_SIZE;
#pragma unroll
        for (int ks = 0; ks < 4; ks++) {
            int k0 = ks * 8;
            unsigned af[4][4], bf[4][2];
#pragma unroll
            for (int mt = 0; mt < 4; mt++) {
                int r = warpM + mt * 16;
                af[mt][0] = __float_as_uint(Ab[(r + gid) * AS_STRIDE + k0 + tg]);
                af[mt][1] = __float_as_uint(Ab[(r + gid + 8) * AS_STRIDE + k0 + tg]);
                af[mt][2] = __float_as_uint(Ab[(r + gid) * AS_STRIDE + k0 + tg + 4]);
                af[mt][3] = __float_as_uint(Ab[(r + gid + 8) * AS_STRIDE + k0 + tg + 4]);
            }
#pragma unroll
            for (int nt = 0; nt < 4; nt++) {
                int c = warpN + nt * 8;
                bf[nt][0] = __float_as_uint(Bb[(k0 + tg) * BS_STRIDE + c + gid]);
                bf[nt][1] = __float_as_uint(Bb[(k0 + tg + 4) * BS_STRIDE + c + gid]);
            }
#pragma unroll
            for (int mt = 0; mt < 4; mt++)
#pragma unroll
                for (int nt = 0; nt < 4; nt++) {
                    asm volatile(
                        "mma.sync.aligned.m16n8k8.row.col.f32.tf32.tf32.f32 "
                        "{%0,%1,%2,%3}, {%4,%5,%6,%7}, {%8,%9}, {%0,%1,%2,%3};"
                        : "+f"(acc[mt][nt][0]), "+f"(acc[mt][nt][1]),
                          "+f"(acc[mt][nt][2]), "+f"(acc[mt][nt][3])
                        : "r"(af[mt][0]), "r"(af[mt][1]), "r"(af[mt][2]), "r"(af[mt][3]),
                          "r"(bf[nt][0]), "r"(bf[nt][1]));
                }
        }
        buf++; if (buf >= 3) buf -= 3;
    }

    // epilogue
#pragma unroll
    for (int mt = 0; mt < 4; mt++) {
#pragma unroll
        for (int nt = 0; nt < 4; nt++) {
            int r0 = rowBase + warpM + mt * 16 + gid;
            int c0 = colBase + warpN + nt * 8 + tg * 2;
#pragma unroll
            for (int half = 0; half < 2; half++) {
                int row = r0 + half * 8;
                if (row < M) {
#pragma unroll
                    for (int j = 0; j < 2; j++) {
                        int col = c0 + j;
                        if (col < Nn) {
                            float v = acc[mt][nt][half * 2 + j] + bias[col];
                            if (relu) v = fmaxf(v, 0.f);
                            if (round_out) v = rna_tf32(v);
                            C[(size_t)row * Nn + col] = v;
                        }
                    }
                }
            }
        }
    }
}

// ---------------- GATv2 aggregation: 2 nodes / block, 2 edges / iteration ----
// Warps 0-3 handle node 2b; warps 4-7 node 2b+1. One We_sh serves both.
// Each inner iteration processes TWO edges sharing one set of We smem reads
// (halves the dominant smem-crossbar traffic). One-pair-ahead prefetch.
__global__ __launch_bounds__(256) void gat_kernel(
    const float* __restrict__ xlr,        // [N][1024] xl|xr
    const float* __restrict__ edge_attr,  // [E][16]
    const float* __restrict__ We,         // [16][512]
    const float* __restrict__ att,        // [512]
    const float* __restrict__ bias,       // [512]
    float* __restrict__ out)              // [N][512] (tf32-rounded: feeds GEMMs only)
{
    __shared__ float We_sh[EDGE_D * HC];
    for (int i = threadIdx.x; i < EDGE_D * HC; i += 256) We_sh[i] = We[i];
    __syncthreads();

    int w = (threadIdx.x >> 5) & 3;           // head
    int lane = threadIdx.x & 31;
    int n = blockIdx.x * 2 + (threadIdx.x >> 7);   // node
    if (n >= NN) return;
    int cbase = w * EMB + lane;
    const float* Wp = We_sh + cbase;

    float att0 = __ldg(&att[cbase]);
    float att1 = __ldg(&att[cbase + 32]);
    float att2 = __ldg(&att[cbase + 64]);
    float att3 = __ldg(&att[cbase + 96]);

    const float* xrp = xlr + (size_t)n * 1024 + HC + cbase;
    float xr0 = xrp[0], xr1 = xrp[32], xr2 = xrp[64], xr3 = xrp[96];

    float m = -CUDART_INF_F, den = 0.f;
    float a0 = 0.f, a1 = 0.f, a2 = 0.f, a3 = 0.f;

    int beg = g_off[n], end = g_off[n + 1];

#define LOAD_EDGE(IDX, SRC, EAV) do {                                        \
        const float* _ea;                                                    \
        if ((IDX) < end) {                                                   \
            SRC = __ldg(&g_csr_src[IDX]);                                    \
            _ea = edge_attr + (size_t)__ldg(&g_csr_eid[IDX]) * EDGE_D;       \
        } else {                                                             \
            SRC = n;                                                         \
            _ea = g_loop + (size_t)n * EDGE_D;                               \
        }                                                                    \
        EAV = (lane < EDGE_D) ? __ldg(&_ea[lane]) : 0.f;                     \
    } while (0)

#define LOAD_X(SRC, X0, X1, X2, X3) do {                                     \
        const float* _xp = xlr + (size_t)(SRC) * 1024 + cbase;               \
        X0 = __ldg(&_xp[0]);  X1 = __ldg(&_xp[32]);                          \
        X2 = __ldg(&_xp[64]); X3 = __ldg(&_xp[96]);                          \
    } while (0)

    // pair pipeline state (current + next)
    float ceA, ceB, nceA, nceB;
    float ca0, ca1, ca2, ca3, cb0, cb1, cb2, cb3;
    float na0, na1, na2, na3, nb0, nb1, nb2, nb3;

    {
        int s;
        LOAD_EDGE(beg, s, nceA);
        LOAD_X(s, na0, na1, na2, na3);
        if (beg + 1 <= end) {
            LOAD_EDGE(beg + 1, s, nceB);
            LOAD_X(s, nb0, nb1, nb2, nb3);
        } else {
            nceB = 0.f; nb0 = nb1 = nb2 = nb3 = 0.f;
        }
    }

    for (int i = beg; i <= end; i += 2) {
        ceA = nceA; ceB = nceB;
        ca0 = na0; ca1 = na1; ca2 = na2; ca3 = na3;
        cb0 = nb0; cb1 = nb1; cb2 = nb2; cb3 = nb3;
        bool validB = (i + 1 <= end);

        // prefetch next pair
        if (i + 2 <= end) {
            int s;
            LOAD_EDGE(i + 2, s, nceA);
            LOAD_X(s, na0, na1, na2, na3);
            if (i + 3 <= end) {
                LOAD_EDGE(i + 3, s, nceB);
                LOAD_X(s, nb0, nb1, nb2, nb3);
            } else {
                nceB = 0.f; nb0 = nb1 = nb2 = nb3 = 0.f;
            }
        }

        float eA0 = xr0, eA1 = xr1, eA2 = xr2, eA3 = xr3;
        float eB0 = xr0, eB1 = xr1, eB2 = xr2, eB3 = xr3;
#pragma unroll
        for (int d = 0; d < EDGE_D; d++) {
            float avA = __shfl_sync(0xffffffffu, ceA, d);
            float avB = __shfl_sync(0xffffffffu, ceB, d);
            float w0 = Wp[d * HC];
            float w1 = Wp[d * HC + 32];
            float w2 = Wp[d * HC + 64];
            float w3 = Wp[d * HC + 96];
            eA0 = fmaf(avA, w0, eA0); eB0 = fmaf(avB, w0, eB0);
            eA1 = fmaf(avA, w1, eA1); eB1 = fmaf(avB, w1, eB1);
            eA2 = fmaf(avA, w2, eA2); eB2 = fmaf(avB, w2, eB2);
            eA3 = fmaf(avA, w3, eA3); eB3 = fmaf(avB, w3, eB3);
        }
        float sA0 = ca0 + eA0, sA1 = ca1 + eA1, sA2 = ca2 + eA2, sA3 = ca3 + eA3;
        float sB0 = cb0 + eB0, sB1 = cb1 + eB1, sB2 = cb2 + eB2, sB3 = cb3 + eB3;
        float lA0 = fmaxf(sA0, NEG_SLOPE * sA0), lA1 = fmaxf(sA1, NEG_SLOPE * sA1);
        float lA2 = fmaxf(sA2, NEG_SLOPE * sA2), lA3 = fmaxf(sA3, NEG_SLOPE * sA3);
        float lB0 = fmaxf(sB0, NEG_SLOPE * sB0), lB1 = fmaxf(sB1, NEG_SLOPE * sB1);
        float lB2 = fmaxf(sB2, NEG_SLOPE * sB2), lB3 = fmaxf(sB3, NEG_SLOPE * sB3);

        float pA = lA0 * att0;
        pA = fmaf(lA1, att1, pA); pA = fmaf(lA2, att2, pA); pA = fmaf(lA3, att3, pA);
        float pB = lB0 * att0;
        pB = fmaf(lB1, att1, pB); pB = fmaf(lB2, att2, pB); pB = fmaf(lB3, att3, pB);
#pragma unroll
        for (int o = 16; o > 0; o >>= 1) {
            pA += __shfl_xor_sync(0xffffffffu, pA, o);
            pB += __shfl_xor_sync(0xffffffffu, pB, o);
        }
        if (!validB) pB = -CUDART_INF_F;

        float nm = fmaxf(m, fmaxf(pA, pB));
        float corr = __expf(m - nm);
        float peA  = __expf(pA - nm);
        float peB  = __expf(pB - nm);      // 0 when pB = -inf
        den = den * corr + peA + peB;
        a0 = a0 * corr + peA * ca0 + peB * cb0;
        a1 = a1 * corr + peA * ca1 + peB * cb1;
        a2 = a2 * corr + peA * ca2 + peB * cb2;
        a3 = a3 * corr + peA * ca3 + peB * cb3;
        m = nm;
    }
    float inv = 1.f / (den + 1e-16f);
    float* op = out + (size_t)n * HC + cbase;
    op[0]  = rna_tf32(fmaf(a0, inv, __ldg(&bias[cbase])));
    op[32] = rna_tf32(fmaf(a1, inv, __ldg(&bias[cbase + 32])));
    op[64] = rna_tf32(fmaf(a2, inv, __ldg(&bias[cbase + 64])));
    op[96] = rna_tf32(fmaf(a3, inv, __ldg(&bias[cbase + 96])));
#undef LOAD_EDGE
#undef LOAD_X
}

// ---------------- launch ------------------------------------------------------
extern "C" void kernel_launch(void* const* d_in, const int* in_sizes, int n_in,
                              void* d_out, int out_size) {
    const float* x     = (const float*)d_in[0];
    const void*  eidx  = d_in[1];
    const float* eattr = (const float*)d_in[2];
    const float* Wl1   = (const float*)d_in[3];
    const float* bl1   = (const float*)d_in[4];
    const float* Wr1   = (const float*)d_in[5];
    const float* br1   = (const float*)d_in[6];
    const float* We1   = (const float*)d_in[7];
    const float* att1  = (const float*)d_in[8];
    const float* bias1 = (const float*)d_in[9];
    const float* Wl2   = (const float*)d_in[10];
    const float* bl2   = (const float*)d_in[11];
    const float* Wr2   = (const float*)d_in[12];
    const float* br2   = (const float*)d_in[13];
    const float* We2   = (const float*)d_in[14];
    const float* att2  = (const float*)d_in[15];
    const float* bias2 = (const float*)d_in[16];
    const float* Wd1   = (const float*)d_in[17];
    const float* bd1   = (const float*)d_in[18];
    const float* Wd2   = (const float*)d_in[19];
    const float* bd2   = (const float*)d_in[20];
    float* out = (float*)d_out;

    float* xlr; cudaGetSymbolAddress((void**)&xlr, g_xlr);
    float* h;   cudaGetSymbolAddress((void**)&h, g_h);
    float* xA;  cudaGetSymbolAddress((void**)&xA, g_xA);
    float* Wp;  cudaGetSymbolAddress((void**)&Wp, g_Wp);
    float* bp;  cudaGetSymbolAddress((void**)&bp, g_bp);

    cudaFuncSetAttribute(gemm_tc_kernel,
                         cudaFuncAttributeMaxDynamicSharedMemorySize, GEMM_SMEM);

    dim3 blk(256);
    dim3 grid_lr(1024 / BNt, (NN + BMt - 1) / BMt);
    dim3 grid_d1((HIDDEN + BNt - 1) / BNt, (NN + BMt - 1) / BMt);
    dim3 grid_d2((OUTD + BNt - 1) / BNt, (NN + BMt - 1) / BMt);

    // ---- layer-1 GEMM first (ncu capture lands here) ----
    init_kernel<<<(NN + 255) / 256, 256>>>(eidx);
    round_x_kernel<<<(NN * NODE_D + 255) / 256, 256>>>(x);
    pack_kernel<<<(NODE_D * 1024 + 255) / 256, 256>>>(Wl1, Wr1, bl1, br1, HC, 1024, NODE_D);
    gemm_tc_kernel<<<grid_lr, blk, GEMM_SMEM>>>(xA, Wp, bp, xlr, NN, 1024, NODE_D, 0, 0);

    // ---- CSR preprocessing ----
    count_kernel<<<(EE + 255) / 256, 256>>>(eidx);
    scan_kernel<<<1, 1024>>>();
    scatter_kernel<<<(EE + 255) / 256, 256>>>(eidx);
    loopattr_kernel<<<(NN + 3) / 4, 128>>>(eattr);

    // ---- layer 1 aggregation ----
    gat_kernel<<<NN / 2, 256>>>(xlr, eattr, We1, att1, bias1, h);

    // ---- layer 2 ----
    pack_kernel<<<(HC * 1024 + 255) / 256, 256>>>(Wl2, Wr2, bl2, br2, HC, 1024, HC);
    gemm_tc_kernel<<<grid_lr, blk, GEMM_SMEM>>>(h, Wp, bp, xlr, NN, 1024, HC, 0, 0);
    gat_kernel<<<NN / 2, 256>>>(xlr, eattr, We2, att2, bias2, h);

    // ---- decoder ----
    float* hid = xlr;  // reuse scratch
    pack_kernel<<<(HC * HIDDEN + 255) / 256, 256>>>(Wd1, Wd1, bd1, bd1, HIDDEN, HIDDEN, HC);
    gemm_tc_kernel<<<grid_d1, blk, GEMM_SMEM>>>(h, Wp, bp, hid, NN, HIDDEN, HC, 1, 1);
    pack_kernel<<<(HIDDEN * OUTD + 255) / 256, 256>>>(Wd2, Wd2, bd2, bd2, OUTD, OUTD, HIDDEN);
    gemm_tc_kernel<<<grid_d2, blk, GEMM_SMEM>>>(hid, Wp, bp, out, NN, OUTD, HIDDEN, 0, 0);
}

// round 14
// speedup vs baseline: 2.1364x; 1.0237x over previous
#include <cuda_runtime.h>
#include <cuda_bf16.h>
#include <math_constants.h>
#include <cstdint>

// Problem constants
#define NN      20000
#define EE      320000
#define NODE_D  128
#define EDGE_D  16
#define HC      512       // HEADS*EMB
#define HEADS   4
#define EMB     128
#define HIDDEN  512
#define OUTD    64
#define NEG_SLOPE 0.2f

// ---------------- scratch (device globals; no allocation allowed) -------------
__device__ int   g_is64;
__device__ int   g_cnt[NN];
__device__ int   g_off[NN + 1];
__device__ int   g_cur[NN];
__device__ int   g_csr_src[EE];
__device__ int   g_csr_eid[EE];
__device__ float g_loop[NN * EDGE_D];
__device__ float g_Wp[HC * 1024];             // packed+rounded weights (max 512x1024)
__device__ float g_bp[1024];                  // packed bias
__device__ float g_xA[(size_t)NN * NODE_D];   // tf32-rounded copy of x
__device__ float g_xlr[(size_t)NN * 1024];    // [N][1024]: xl | xr (reused as decoder hidden)
__device__ float g_h[(size_t)NN * HC];        // layer outputs (tf32-rounded)

// ---------------- helpers -----------------------------------------------------
__device__ __forceinline__ int edge_val(const void* p, int is64, long long i) {
    return is64 ? (int)((const long long*)p)[i] : ((const int*)p)[i];
}

__device__ __forceinline__ float rna_tf32(float f) {
    unsigned u;
    asm("cvt.rna.tf32.f32 %0, %1;" : "=r"(u) : "f"(f));
    return __uint_as_float(u);
}

// zero counters + detect int64 vs int32 edge_index
__global__ void init_kernel(const void* eidx) {
    int i = blockIdx.x * blockDim.x + threadIdx.x;
    if (i < NN) { g_cnt[i] = 0; g_cur[i] = 0; }
    if (i == 0) {
        const unsigned* p = (const unsigned*)eidx;
        int is64 = 1;
        for (int k = 0; k < 16; k++)
            if (p[2 * k + 1] != 0u) is64 = 0;
        g_is64 = is64;
    }
}

__global__ void count_kernel(const void* eidx) {
    int e = blockIdx.x * blockDim.x + threadIdx.x;
    if (e >= EE) return;
    int is64 = g_is64;
    int dst = edge_val(eidx, is64, (long long)EE + e);
    atomicAdd(&g_cnt[dst], 1);
}

__global__ __launch_bounds__(1024) void scan_kernel() {
    __shared__ int s[1024];
    int tid = threadIdx.x;
    const int per = (NN + 1023) >> 10;
    int start = tid * per;
    int sum = 0;
    for (int i = 0; i < per; i++) {
        int idx = start + i;
        if (idx < NN) sum += g_cnt[idx];
    }
    s[tid] = sum;
    __syncthreads();
    for (int o = 1; o < 1024; o <<= 1) {
        int v = 0;
        if (tid >= o) v = s[tid - o];
        __syncthreads();
        if (tid >= o) s[tid] += v;
        __syncthreads();
    }
    int base = (tid > 0) ? s[tid - 1] : 0;
    for (int i = 0; i < per; i++) {
        int idx = start + i;
        if (idx < NN) { g_off[idx] = base; base += g_cnt[idx]; }
    }
    if (tid == 1023) g_off[NN] = s[1023];
}

__global__ void scatter_kernel(const void* eidx) {
    int e = blockIdx.x * blockDim.x + threadIdx.x;
    if (e >= EE) return;
    int is64 = g_is64;
    int src = edge_val(eidx, is64, e);
    int dst = edge_val(eidx, is64, (long long)EE + e);
    int pos = g_off[dst] + atomicAdd(&g_cur[dst], 1);
    g_csr_src[pos] = src;
    g_csr_eid[pos] = e;
}

// self-loop attr = mean of incoming edge_attr (CSR-based, no atomics)
__global__ __launch_bounds__(128) void loopattr_kernel(const float* __restrict__ ea) {
    int n = blockIdx.x * 4 + (threadIdx.x >> 5);
    if (n >= NN) return;
    int lane = threadIdx.x & 31;
    int beg = g_off[n], end = g_off[n + 1];
    float sum = 0.f;
    if (lane < EDGE_D) {
        for (int i = beg; i < end; i++) {
            int eid = g_csr_eid[i];
            sum += __ldg(&ea[(size_t)eid * EDGE_D + lane]);
        }
        float c = (float)(end - beg);
        g_loop[n * EDGE_D + lane] = sum / fmaxf(c, 1.f);
    }
}

// tf32-round x into g_xA
__global__ void round_x_kernel(const float* __restrict__ x) {
    int i = blockIdx.x * blockDim.x + threadIdx.x;
    if (i < NN * NODE_D) g_xA[i] = rna_tf32(x[i]);
}

// pack [W0|W1] (split at col S) into g_Wp with tf32 rounding; bias into g_bp
__global__ void pack_kernel(const float* __restrict__ W0, const float* __restrict__ W1,
                            const float* __restrict__ b0, const float* __restrict__ b1,
                            int S, int Nn, int K) {
    int i = blockIdx.x * blockDim.x + threadIdx.x;
    if (i < K * Nn) {
        int k = i / Nn, j = i - k * Nn;
        float v = (j < S) ? W0[k * S + j] : W1[k * (Nn - S) + (j - S)];
        g_Wp[i] = rna_tf32(v);
    }
    if (i < Nn) g_bp[i] = (i < S) ? b0[i] : b1[i - S];
}

// ---------------- tf32 tensor-core GEMM (3-stage cp.async pipeline) -----------
// Operands must already be tf32-rounded in memory. 256 threads, 64x32 warp tile.
#define BMt 128
#define BNt 128
#define BKt 32
#define AS_STRIDE 36
#define BS_STRIDE 136
#define AS_SIZE (BMt * AS_STRIDE)            // floats
#define BS_SIZE (BKt * BS_STRIDE)
#define STAGE_FLOATS (AS_SIZE + BS_SIZE)     // 8960 floats = 35840 B
#define GEMM_SMEM (3 * STAGE_FLOATS * 4)     // 107520 B

__device__ __forceinline__ void cp16(uint32_t dst, const float* src, int sz) {
    asm volatile("cp.async.cg.shared.global [%0], [%1], 16, %2;\n"
                 :: "r"(dst), "l"(src), "r"(sz));
}
__device__ __forceinline__ void cp_commit() {
    asm volatile("cp.async.commit_group;\n" ::: "memory");
}

// 256 threads. A: thread loads row tid>>1, 16-float half (4 x 16B).
// B: thread loads row tid>>3, 16-float chunk (4 x 16B).
__device__ __forceinline__ void load_tiles(
    uint32_t as_u, uint32_t bs_u, const float* aptr, const float* __restrict__ B,
    int kt, int buf, int a_sz, int brow, int colBase, int bcol, int Nn)
{
    uint32_t ad = as_u + buf * (STAGE_FLOATS * 4);
    const float* ap = aptr + kt;
#pragma unroll
    for (int i = 0; i < 4; i++) cp16(ad + i * 16, ap + i * 4, a_sz);
    uint32_t bd = bs_u + buf * (STAGE_FLOATS * 4);
    const float* bp = B + (size_t)(kt + brow) * Nn + colBase + bcol;
#pragma unroll
    for (int i = 0; i < 4; i++) {
        int gcol = colBase + bcol + i * 4;
        cp16(bd + i * 16, bp + i * 4, (gcol < Nn) ? 16 : 0);
    }
}

__global__ __launch_bounds__(256, 2) void gemm_tc_kernel(
    const float* __restrict__ A, const float* __restrict__ B,
    const float* __restrict__ bias, float* __restrict__ C,
    int M, int Nn, int K, int relu, int round_out)
{
    extern __shared__ float sm[];   // 3 stages of [A(128x36) | B(32x136)]

    int tid  = threadIdx.x;
    int warp = tid >> 5;
    int lane = tid & 31;
    int gid  = lane >> 2;
    int tg   = lane & 3;

    int warpM = (warp & 1) * 64;   // 2 warps over M
    int warpN = (warp >> 1) * 32;  // 4 warps over N

    int rowBase = blockIdx.y * BMt;
    int colBase = blockIdx.x * BNt;

    float acc[4][4][4];
#pragma unroll
    for (int i = 0; i < 4; i++)
#pragma unroll
        for (int j = 0; j < 4; j++)
#pragma unroll
            for (int r = 0; r < 4; r++) acc[i][j][r] = 0.f;

    // loader indices
    int arow = tid >> 1;                 // 0..127
    int acol = (tid & 1) * 16;           // 0 or 16
    int brow = tid >> 3;                 // 0..31
    int bcol = (tid & 7) * 16;           // 0..112
    int agrow = rowBase + arow;
    const float* aptr = A + (size_t)agrow * K + acol;
    int a_sz = (agrow < M) ? 16 : 0;

    uint32_t smem_u = (uint32_t)__cvta_generic_to_shared(sm);
    uint32_t as_u = smem_u + (arow * AS_STRIDE + acol) * 4;
    uint32_t bs_u = smem_u + (AS_SIZE + brow * BS_STRIDE + bcol) * 4;

    int nTiles = K / BKt;
    load_tiles(as_u, bs_u, aptr, B, 0, 0, a_sz, brow, colBase, bcol, Nn);
    cp_commit();
    if (nTiles > 1) {
        load_tiles(as_u, bs_u, aptr, B, BKt, 1, a_sz, brow, colBase, bcol, Nn);
        cp_commit();
    }

    int buf = 0;
    for (int t = 0; t < nTiles; t++) {
        if (t + 1 < nTiles) {
            asm volatile("cp.async.wait_group 1;\n" ::: "memory");
        } else {
            asm volatile("cp.async.wait_group 0;\n" ::: "memory");
        }
        __syncthreads();

        if (t + 2 < nTiles) {
            int nbuf = buf + 2; if (nbuf >= 3) nbuf -= 3;
            load_tiles(as_u, bs_u, aptr, B, (t + 2) * BKt, nbuf, a_sz, brow, colBase, bcol, Nn);
            cp_commit();
        }

        const float* Ab = sm + buf * STAGE_FLOATS;
        const float* Bb = Ab + AS_SIZE;
#pragma unroll
        for (int ks = 0; ks < 4; ks++) {
            int k0 = ks * 8;
            unsigned af[4][4], bf[4][2];
#pragma unroll
            for (int mt = 0; mt < 4; mt++) {
                int r = warpM + mt * 16;
                af[mt][0] = __float_as_uint(Ab[(r + gid) * AS_STRIDE + k0 + tg]);
                af[mt][1] = __float_as_uint(Ab[(r + gid + 8) * AS_STRIDE + k0 + tg]);
                af[mt][2] = __float_as_uint(Ab[(r + gid) * AS_STRIDE + k0 + tg + 4]);
                af[mt][3] = __float_as_uint(Ab[(r + gid + 8) * AS_STRIDE + k0 + tg + 4]);
            }
#pragma unroll
            for (int nt = 0; nt < 4; nt++) {
                int c = warpN + nt * 8;
                bf[nt][0] = __float_as_uint(Bb[(k0 + tg) * BS_STRIDE + c + gid]);
                bf[nt][1] = __float_as_uint(Bb[(k0 + tg + 4) * BS_STRIDE + c + gid]);
            }
#pragma unroll
            for (int mt = 0; mt < 4; mt++)
#pragma unroll
                for (int nt = 0; nt < 4; nt++) {
                    asm volatile(
                        "mma.sync.aligned.m16n8k8.row.col.f32.tf32.tf32.f32 "
                        "{%0,%1,%2,%3}, {%4,%5,%6,%7}, {%8,%9}, {%0,%1,%2,%3};"
                        : "+f"(acc[mt][nt][0]), "+f"(acc[mt][nt][1]),
                          "+f"(acc[mt][nt][2]), "+f"(acc[mt][nt][3])
                        : "r"(af[mt][0]), "r"(af[mt][1]), "r"(af[mt][2]), "r"(af[mt][3]),
                          "r"(bf[nt][0]), "r"(bf[nt][1]));
                }
        }
        buf++; if (buf >= 3) buf -= 3;
    }

    // epilogue
#pragma unroll
    for (int mt = 0; mt < 4; mt++) {
#pragma unroll
        for (int nt = 0; nt < 4; nt++) {
            int r0 = rowBase + warpM + mt * 16 + gid;
            int c0 = colBase + warpN + nt * 8 + tg * 2;
#pragma unroll
            for (int half = 0; half < 2; half++) {
                int row = r0 + half * 8;
                if (row < M) {
#pragma unroll
                    for (int j = 0; j < 2; j++) {
                        int col = c0 + j;
                        if (col < Nn) {
                            float v = acc[mt][nt][half * 2 + j] + bias[col];
                            if (relu) v = fmaxf(v, 0.f);
                            if (round_out) v = rna_tf32(v);
                            C[(size_t)row * Nn + col] = v;
                        }
                    }
                }
            }
        }
    }
}

// ---------------- GATv2 aggregation: 2 nodes / block, 4 edges / iteration ----
// Warps 0-3 handle node 2b; warps 4-7 node 2b+1. One We_sh serves both.
// Each inner iteration processes FOUR edges sharing one set of We smem reads
// (quarters the dominant smem-crossbar traffic). No cross-iteration prefetch
// (R12 showed warp concurrency already covers gather latency).
__global__ __launch_bounds__(256) void gat_kernel(
    const float* __restrict__ xlr,        // [N][1024] xl|xr
    const float* __restrict__ edge_attr,  // [E][16]
    const float* __restrict__ We,         // [16][512]
    const float* __restrict__ att,        // [512]
    const float* __restrict__ bias,       // [512]
    float* __restrict__ out)              // [N][512] (tf32-rounded: feeds GEMMs only)
{
    __shared__ float We_sh[EDGE_D * HC];
    for (int i = threadIdx.x; i < EDGE_D * HC; i += 256) We_sh[i] = We[i];
    __syncthreads();

    int w = (threadIdx.x >> 5) & 3;           // head
    int lane = threadIdx.x & 31;
    int n = blockIdx.x * 2 + (threadIdx.x >> 7);   // node
    if (n >= NN) return;
    int cbase = w * EMB + lane;
    const float* Wp = We_sh + cbase;

    float att0 = __ldg(&att[cbase]);
    float att1 = __ldg(&att[cbase + 32]);
    float att2 = __ldg(&att[cbase + 64]);
    float att3 = __ldg(&att[cbase + 96]);

    const float* xrp = xlr + (size_t)n * 1024 + HC + cbase;
    float xr0 = xrp[0], xr1 = xrp[32], xr2 = xrp[64], xr3 = xrp[96];

    float m = -CUDART_INF_F, den = 0.f;
    float a0 = 0.f, a1 = 0.f, a2 = 0.f, a3 = 0.f;

    int beg = g_off[n], end = g_off[n + 1];

    for (int i = beg; i <= end; i += 4) {
        // load up to 4 edges (invalid slots -> zeros; masked out at softmax)
        float ce[4];
        float cx[4][4];
#pragma unroll
        for (int j = 0; j < 4; j++) {
            int idx = i + j;
            if (idx <= end) {
                int src;
                const float* ea;
                if (idx < end) {
                    src = __ldg(&g_csr_src[idx]);
                    ea  = edge_attr + (size_t)__ldg(&g_csr_eid[idx]) * EDGE_D;
                } else {
                    src = n;
                    ea  = g_loop + (size_t)n * EDGE_D;
                }
                ce[j] = (lane < EDGE_D) ? __ldg(&ea[lane]) : 0.f;
                const float* xp = xlr + (size_t)src * 1024 + cbase;
                cx[j][0] = __ldg(&xp[0]);  cx[j][1] = __ldg(&xp[32]);
                cx[j][2] = __ldg(&xp[64]); cx[j][3] = __ldg(&xp[96]);
            } else {
                ce[j] = 0.f;
                cx[j][0] = cx[j][1] = cx[j][2] = cx[j][3] = 0.f;
            }
        }

        // ef accumulators (init with xr)
        float e[4][4];
#pragma unroll
        for (int j = 0; j < 4; j++) {
            e[j][0] = xr0; e[j][1] = xr1; e[j][2] = xr2; e[j][3] = xr3;
        }
#pragma unroll
        for (int d = 0; d < EDGE_D; d++) {
            float w0 = Wp[d * HC];
            float w1 = Wp[d * HC + 32];
            float w2 = Wp[d * HC + 64];
            float w3 = Wp[d * HC + 96];
#pragma unroll
            for (int j = 0; j < 4; j++) {
                float av = __shfl_sync(0xffffffffu, ce[j], d);
                e[j][0] = fmaf(av, w0, e[j][0]);
                e[j][1] = fmaf(av, w1, e[j][1]);
                e[j][2] = fmaf(av, w2, e[j][2]);
                e[j][3] = fmaf(av, w3, e[j][3]);
            }
        }

        float p[4];
#pragma unroll
        for (int j = 0; j < 4; j++) {
            float s0 = cx[j][0] + e[j][0];
            float s1 = cx[j][1] + e[j][1];
            float s2 = cx[j][2] + e[j][2];
            float s3 = cx[j][3] + e[j][3];
            float l0 = fmaxf(s0, NEG_SLOPE * s0);
            float l1 = fmaxf(s1, NEG_SLOPE * s1);
            float l2 = fmaxf(s2, NEG_SLOPE * s2);
            float l3 = fmaxf(s3, NEG_SLOPE * s3);
            float pv = l0 * att0;
            pv = fmaf(l1, att1, pv);
            pv = fmaf(l2, att2, pv);
            pv = fmaf(l3, att3, pv);
            p[j] = pv;
        }
#pragma unroll
        for (int o = 16; o > 0; o >>= 1) {
#pragma unroll
            for (int j = 0; j < 4; j++)
                p[j] += __shfl_xor_sync(0xffffffffu, p[j], o);
        }
#pragma unroll
        for (int j = 0; j < 4; j++)
            if (i + j > end) p[j] = -CUDART_INF_F;

        float nm = fmaxf(fmaxf(m, fmaxf(p[0], p[1])), fmaxf(p[2], p[3]));
        float corr = __expf(m - nm);
        float pe0 = __expf(p[0] - nm);
        float pe1 = __expf(p[1] - nm);
        float pe2 = __expf(p[2] - nm);
        float pe3 = __expf(p[3] - nm);
        den = den * corr + pe0 + pe1 + pe2 + pe3;
        a0 = a0 * corr + pe0 * cx[0][0] + pe1 * cx[1][0] + pe2 * cx[2][0] + pe3 * cx[3][0];
        a1 = a1 * corr + pe0 * cx[0][1] + pe1 * cx[1][1] + pe2 * cx[2][1] + pe3 * cx[3][1];
        a2 = a2 * corr + pe0 * cx[0][2] + pe1 * cx[1][2] + pe2 * cx[2][2] + pe3 * cx[3][2];
        a3 = a3 * corr + pe0 * cx[0][3] + pe1 * cx[1][3] + pe2 * cx[2][3] + pe3 * cx[3][3];
        m = nm;
    }
    float inv = 1.f / (den + 1e-16f);
    float* op = out + (size_t)n * HC + cbase;
    op[0]  = rna_tf32(fmaf(a0, inv, __ldg(&bias[cbase])));
    op[32] = rna_tf32(fmaf(a1, inv, __ldg(&bias[cbase + 32])));
    op[64] = rna_tf32(fmaf(a2, inv, __ldg(&bias[cbase + 64])));
    op[96] = rna_tf32(fmaf(a3, inv, __ldg(&bias[cbase + 96])));
}

// ---------------- launch ------------------------------------------------------
extern "C" void kernel_launch(void* const* d_in, const int* in_sizes, int n_in,
                              void* d_out, int out_size) {
    const float* x     = (const float*)d_in[0];
    const void*  eidx  = d_in[1];
    const float* eattr = (const float*)d_in[2];
    const float* Wl1   = (const float*)d_in[3];
    const float* bl1   = (const float*)d_in[4];
    const float* Wr1   = (const float*)d_in[5];
    const float* br1   = (const float*)d_in[6];
    const float* We1   = (const float*)d_in[7];
    const float* att1  = (const float*)d_in[8];
    const float* bias1 = (const float*)d_in[9];
    const float* Wl2   = (const float*)d_in[10];
    const float* bl2   = (const float*)d_in[11];
    const float* Wr2   = (const float*)d_in[12];
    const float* br2   = (const float*)d_in[13];
    const float* We2   = (const float*)d_in[14];
    const float* att2  = (const float*)d_in[15];
    const float* bias2 = (const float*)d_in[16];
    const float* Wd1   = (const float*)d_in[17];
    const float* bd1   = (const float*)d_in[18];
    const float* Wd2   = (const float*)d_in[19];
    const float* bd2   = (const float*)d_in[20];
    float* out = (float*)d_out;

    float* xlr; cudaGetSymbolAddress((void**)&xlr, g_xlr);
    float* h;   cudaGetSymbolAddress((void**)&h, g_h);
    float* xA;  cudaGetSymbolAddress((void**)&xA, g_xA);
    float* Wp;  cudaGetSymbolAddress((void**)&Wp, g_Wp);
    float* bp;  cudaGetSymbolAddress((void**)&bp, g_bp);

    cudaFuncSetAttribute(gemm_tc_kernel,
                         cudaFuncAttributeMaxDynamicSharedMemorySize, GEMM_SMEM);

    dim3 blk(256);
    dim3 grid_lr(1024 / BNt, (NN + BMt - 1) / BMt);
    dim3 grid_d1((HIDDEN + BNt - 1) / BNt, (NN + BMt - 1) / BMt);
    dim3 grid_d2((OUTD + BNt - 1) / BNt, (NN + BMt - 1) / BMt);

    // ---- layer-1 GEMM first (ncu capture lands here) ----
    init_kernel<<<(NN + 255) / 256, 256>>>(eidx);
    round_x_kernel<<<(NN * NODE_D + 255) / 256, 256>>>(x);
    pack_kernel<<<(NODE_D * 1024 + 255) / 256, 256>>>(Wl1, Wr1, bl1, br1, HC, 1024, NODE_D);
    gemm_tc_kernel<<<grid_lr, blk, GEMM_SMEM>>>(xA, Wp, bp, xlr, NN, 1024, NODE_D, 0, 0);

    // ---- CSR preprocessing ----
    count_kernel<<<(EE + 255) / 256, 256>>>(eidx);
    scan_kernel<<<1, 1024>>>();
    scatter_kernel<<<(EE + 255) / 256, 256>>>(eidx);
    loopattr_kernel<<<(NN + 3) / 4, 128>>>(eattr);

    // ---- layer 1 aggregation ----
    gat_kernel<<<NN / 2, 256>>>(xlr, eattr, We1, att1, bias1, h);

    // ---- layer 2 ----
    pack_kernel<<<(HC * 1024 + 255) / 256, 256>>>(Wl2, Wr2, bl2, br2, HC, 1024, HC);
    gemm_tc_kernel<<<grid_lr, blk, GEMM_SMEM>>>(h, Wp, bp, xlr, NN, 1024, HC, 0, 0);
    gat_kernel<<<NN / 2, 256>>>(xlr, eattr, We2, att2, bias2, h);

    // ---- decoder ----
    float* hid = xlr;  // reuse scratch
    pack_kernel<<<(HC * HIDDEN + 255) / 256, 256>>>(Wd1, Wd1, bd1, bd1, HIDDEN, HIDDEN, HC);
    gemm_tc_kernel<<<grid_d1, blk, GEMM_SMEM>>>(h, Wp, bp, hid, NN, HIDDEN, HC, 1, 1);
    pack_kernel<<<(HIDDEN * OUTD + 255) / 256, 256>>>(Wd2, Wd2, bd2, bd2, OUTD, OUTD, HIDDEN);
    gemm_tc_kernel<<<grid_d2, blk, GEMM_SMEM>>>(hid, Wp, bp, out, NN, OUTD, HIDDEN, 0, 0);
}